// round 10
// baseline (speedup 1.0000x reference)
#include <cuda_runtime.h>
#include <cuda_bf16.h>
#include <math.h>
#include <cstdint>

// ---------------------------------------------------------------------------
// SlotAttention: b=32, n=1024, c=256, d=256, S=8 slots, 3 iters.
// KV projection: bf16 m16n8k16 mma.sync (tcgen05 unavailable: harness builds
// through compute_103 PTX which rejects tcgen05). LN folded into epilogues.
// ---------------------------------------------------------------------------
#define Bsz 32
#define NTOK 1024
#define NSLOT 8
#define ITERS 3
#define TOKROWS (Bsz*NTOK)      // 32768
#define SROWS (Bsz*NSLOT)       // 256
#define SCALE_F 0.0625f
#define EPS_F 1e-8f
#define NCHUNK 8                // attn j-chunks of 128

// scratch arena (floats)
#define OFF_KV     0                                  // 32768*512
#define OFF_SLOTS  (OFF_KV + TOKROWS*512)             // 256*256
#define OFF_GBUF   (OFF_SLOTS + SROWS*256)
#define OFF_U      (OFF_GBUF + SROWS*256)
#define OFF_H1     (OFF_U + SROWS*256)                // 256*1024
#define OFF_UPDP   (OFF_H1 + SROWS*1024)              // 8*256*256
#define OFF_RSP    (OFF_UPDP + NCHUNK*SROWS*256)      // 8*256
#define OFF_S1KV   (OFF_RSP + NCHUNK*SROWS)           // 512
#define OFF_S2KV   (OFF_S1KV + 512)
#define OFF_WQT    (OFF_S2KV + 512)                   // 256*256
#define OFF_S1Q    (OFF_WQT + 256*256)
#define OFF_S2Q    (OFF_S1Q + 256)
#define OFF_W1P    (OFF_S2Q + 256)                    // 1024*256
#define OFF_S1M    (OFF_W1P + 1024*256)
#define OFF_S2M    (OFF_S1M + 1024)
#define SCRATCH_FLOATS (OFF_S2M + 1024)

__device__ float g_scratch[SCRATCH_FLOATS];
// bf16 g-scaled stacked [Wk;Wv], row-major [512][256]
__device__ __align__(16) __nv_bfloat16 g_wb[512 * 256];

__device__ __forceinline__ float warp_sum(float v) {
#pragma unroll
    for (int o = 16; o > 0; o >>= 1) v += __shfl_xor_sync(0xffffffffu, v, o);
    return v;
}
__device__ __forceinline__ float grp8_sum(float v) {
    v += __shfl_xor_sync(0xffffffffu, v, 4);
    v += __shfl_xor_sync(0xffffffffu, v, 2);
    v += __shfl_xor_sync(0xffffffffu, v, 1);
    return v;
}
__device__ __forceinline__ float sigmoidf_(float x) { return 1.0f / (1.0f + __expf(-x)); }

// bf16 m16n8k16 mma.sync
__device__ __forceinline__ void mma16(float* d, const unsigned* a, const unsigned* b) {
    asm volatile("mma.sync.aligned.m16n8k16.row.col.f32.bf16.bf16.f32 "
        "{%0,%1,%2,%3}, {%4,%5,%6,%7}, {%8,%9}, {%0,%1,%2,%3};"
        : "+f"(d[0]), "+f"(d[1]), "+f"(d[2]), "+f"(d[3])
        : "r"(a[0]), "r"(a[1]), "r"(a[2]), "r"(a[3]), "r"(b[0]), "r"(b[1]));
}

// ---------------------------------------------------------------------------
// prep: bf16 g-scaled stacked [Wk;Wv] + S1 (sum of bf16 weights), S2 (bias fold)
// ---------------------------------------------------------------------------
__global__ void prep_kv_kernel(const float* __restrict__ Wk, const float* __restrict__ Wv,
                               const float* __restrict__ g, const float* __restrict__ b,
                               __nv_bfloat16* __restrict__ wb,
                               float* __restrict__ S1, float* __restrict__ S2) {
    int w = threadIdx.x >> 5, lane = threadIdx.x & 31;
    int n = blockIdx.x * 8 + w;                 // 0..511
    const float* src = (n < 256) ? Wk + (size_t)n * 256 : Wv + (size_t)(n - 256) * 256;
    float s1 = 0.f, s2 = 0.f;
#pragma unroll
    for (int u = 0; u < 8; u++) {
        int c = u * 32 + lane;
        __nv_bfloat16 bf = __float2bfloat16(src[c] * g[c]);
        wb[(size_t)n * 256 + c] = bf;
        s1 += __bfloat162float(bf);
        s2 += src[c] * b[c];
    }
    s1 = warp_sum(s1); s2 = warp_sum(s2);
    if (lane == 0) { S1[n] = s1; S2[n] = s2; }
}

// W'q transposed [c][n] (fp32) + S1q/S2q
__global__ void prep_q_kernel(const float* __restrict__ Wq,
                              const float* __restrict__ g, const float* __restrict__ b,
                              float* __restrict__ WqT, float* __restrict__ S1, float* __restrict__ S2) {
    int w = threadIdx.x >> 5, lane = threadIdx.x & 31;
    int n = blockIdx.x * 8 + w;
    float s1 = 0.f, s2 = 0.f;
#pragma unroll
    for (int u = 0; u < 8; u++) {
        int c = u * 32 + lane;
        float wv = Wq[(size_t)n * 256 + c] * g[c];
        WqT[(size_t)c * 256 + n] = wv;
        s1 += wv;
        s2 += Wq[(size_t)n * 256 + c] * b[c];
    }
    s1 = warp_sum(s1); s2 = warp_sum(s2);
    if (lane == 0) { S1[n] = s1; S2[n] = s2; }
}

// W'1 row-major (fp32) + S1m/S2m
__global__ void prep_m1_kernel(const float* __restrict__ W1,
                               const float* __restrict__ g, const float* __restrict__ b,
                               float* __restrict__ W1p, float* __restrict__ S1, float* __restrict__ S2) {
    int w = threadIdx.x >> 5, lane = threadIdx.x & 31;
    int n = blockIdx.x * 8 + w;
    float s1 = 0.f, s2 = 0.f;
#pragma unroll
    for (int u = 0; u < 8; u++) {
        int c = u * 32 + lane;
        float wv = W1[(size_t)n * 256 + c] * g[c];
        W1p[(size_t)n * 256 + c] = wv;
        s1 += wv;
        s2 += W1[(size_t)n * 256 + c] * b[c];
    }
    s1 = warp_sum(s1); s2 = warp_sum(s2);
    if (lane == 0) { S1[n] = s1; S2[n] = s2; }
}

__global__ void init_slots_kernel(const float* __restrict__ mu, const float* __restrict__ ls,
                                  const float* __restrict__ noise, float* __restrict__ slots) {
    int idx = blockIdx.x * blockDim.x + threadIdx.x;
    int d = idx & 255;
    slots[idx] = mu[d] + __expf(ls[d]) * noise[idx];
}

// ---------------------------------------------------------------------------
// KV GEMM: C[32768, 512] = LN(x) @ [W'k;W'v]^T via bf16 m16n8k16 mma.sync.
// BM=128 BN=128 BK=32; warps 2(M)x4(N); warp tile 64x32; LN-fold epilogue
// with in-kernel streamed row stats; register double buffering.
// Smem: bf16 pairs as uint[128][20] (pad-20 -> conflict-free frag loads).
// ---------------------------------------------------------------------------
__global__ __launch_bounds__(256) void kv_mma_kernel(
    const float* __restrict__ x, const __nv_bfloat16* __restrict__ wb,
    const float* __restrict__ S1, const float* __restrict__ S2,
    float* __restrict__ C) {
    __shared__ uint32_t As[128][20];
    __shared__ uint32_t Bs[128][20];
    __shared__ float rowm[128], rowr[128];
    int t = threadIdx.x;
    int bm = blockIdx.y * 128, bn = blockIdx.x * 128;
    int w = t >> 5, lane = t & 31;
    int m0 = (w >> 2) * 64, n0 = (w & 3) * 32;
    int g = lane >> 2, tig = lane & 3;
    float acc[4][4][4];
#pragma unroll
    for (int a = 0; a < 4; a++)
#pragma unroll
        for (int bq = 0; bq < 4; bq++)
#pragma unroll
            for (int c = 0; c < 4; c++) acc[a][bq][c] = 0.f;

    int lm = t >> 3;            // 0..31
    int lkf = (t & 7) * 4;      // float/bf16 col 0..28
    int lku = (t & 7) * 2;      // uint col 0..14

    float4 ar[4]; uint2 br[4];
    float sA[4] = {0.f, 0.f, 0.f, 0.f}, s2A[4] = {0.f, 0.f, 0.f, 0.f};
#pragma unroll
    for (int r = 0; r < 4; r++) {
        ar[r] = *(const float4*)(x + (size_t)(bm + r * 32 + lm) * 256 + lkf);
        br[r] = *(const uint2*)(wb + (size_t)(bn + r * 32 + lm) * 256 + lkf);
    }
    for (int it = 0; it < 8; it++) {
#pragma unroll
        for (int r = 0; r < 4; r++) {
            sA[r] += ar[r].x + ar[r].y + ar[r].z + ar[r].w;
            s2A[r] += ar[r].x * ar[r].x + ar[r].y * ar[r].y + ar[r].z * ar[r].z + ar[r].w * ar[r].w;
        }
        __syncthreads();
#pragma unroll
        for (int r = 0; r < 4; r++) {
            int m = r * 32 + lm;
            __nv_bfloat162 p0 = __floats2bfloat162_rn(ar[r].x, ar[r].y);
            __nv_bfloat162 p1 = __floats2bfloat162_rn(ar[r].z, ar[r].w);
            As[m][lku + 0] = *(uint32_t*)&p0;
            As[m][lku + 1] = *(uint32_t*)&p1;
            Bs[m][lku + 0] = br[r].x;
            Bs[m][lku + 1] = br[r].y;
        }
        __syncthreads();
        if (it < 7) {
            int c = (it + 1) * 32 + lkf;
#pragma unroll
            for (int r = 0; r < 4; r++) {
                ar[r] = *(const float4*)(x + (size_t)(bm + r * 32 + lm) * 256 + c);
                br[r] = *(const uint2*)(wb + (size_t)(bn + r * 32 + lm) * 256 + c);
            }
        }
#pragma unroll
        for (int ks = 0; ks < 2; ks++) {
            unsigned a[4][4], b[4][2];
#pragma unroll
            for (int mt = 0; mt < 4; mt++) {
                int mr = m0 + mt * 16 + g;
                a[mt][0] = As[mr][ks * 8 + tig];
                a[mt][1] = As[mr + 8][ks * 8 + tig];
                a[mt][2] = As[mr][ks * 8 + tig + 4];
                a[mt][3] = As[mr + 8][ks * 8 + tig + 4];
            }
#pragma unroll
            for (int nt = 0; nt < 4; nt++) {
                int nr = n0 + nt * 8 + g;
                b[nt][0] = Bs[nr][ks * 8 + tig];
                b[nt][1] = Bs[nr][ks * 8 + tig + 4];
            }
#pragma unroll
            for (int mt = 0; mt < 4; mt++)
#pragma unroll
                for (int nt = 0; nt < 4; nt++)
                    mma16(acc[mt][nt], a[mt], b[nt]);
        }
    }
    // finalize row stats (8 threads share each row)
#pragma unroll
    for (int r = 0; r < 4; r++) {
        float s = grp8_sum(sA[r]);
        float s2 = grp8_sum(s2A[r]);
        if ((t & 7) == 0) {
            float m = s * (1.0f / 256.0f);
            float var = s2 * (1.0f / 256.0f) - m * m;
            rowm[r * 32 + lm] = m;
            rowr[r * 32 + lm] = rsqrtf(var + 1e-5f);
        }
    }
    __syncthreads();
#pragma unroll
    for (int mt = 0; mt < 4; mt++)
#pragma unroll
        for (int nt = 0; nt < 4; nt++) {
            int lr = m0 + mt * 16 + g;
            int col = bn + n0 + nt * 8 + tig * 2;
            float s1a = S1[col], s1b = S1[col + 1], s2a = S2[col], s2b = S2[col + 1];
            float m0v = rowm[lr], r0v = rowr[lr];
            float m1v = rowm[lr + 8], r1v = rowr[lr + 8];
            float2 o0 = make_float2(r0v * acc[mt][nt][0] - r0v * m0v * s1a + s2a,
                                    r0v * acc[mt][nt][1] - r0v * m0v * s1b + s2b);
            float2 o1 = make_float2(r1v * acc[mt][nt][2] - r1v * m1v * s1a + s2a,
                                    r1v * acc[mt][nt][3] - r1v * m1v * s1b + s2b);
            *(float2*)(C + (size_t)(bm + lr) * 512 + col) = o0;
            *(float2*)(C + (size_t)(bm + lr + 8) * 512 + col) = o1;
        }
}

// ---------------------------------------------------------------------------
// fused attention: LN(slots)->q (via W'qT + epilogue), dots, softmax over
// slots, updates partials + rowsum partials. grid (32 batches, 8 j-chunks).
// ---------------------------------------------------------------------------
__global__ __launch_bounds__(256) void attn_fused_kernel(
    const float* __restrict__ slots, const float* __restrict__ WqT,
    const float* __restrict__ S1q, const float* __restrict__ S2q,
    const float* __restrict__ kv, float* __restrict__ updp, float* __restrict__ rsp) {
    __shared__ float sln[8][256];
    __shared__ float qs[8][256];
    __shared__ float attn_s[128][9];
    __shared__ float rm[8], rr[8], rswarp[8][8];
    int b = blockIdx.x, jc = blockIdx.y;
    int t = threadIdx.x, w = t >> 5, lane = t & 31;

    {
        const float* srow = slots + (size_t)(b * 8 + w) * 256;
        float s = 0.f, s2 = 0.f;
#pragma unroll
        for (int u = 0; u < 8; u++) {
            float v = srow[u * 32 + lane];
            sln[w][u * 32 + lane] = v;
            s += v; s2 += v * v;
        }
        s = warp_sum(s); s2 = warp_sum(s2);
        if (lane == 0) {
            float m = s * (1.0f / 256.0f);
            float var = s2 * (1.0f / 256.0f) - m * m;
            rm[w] = m; rr[w] = rsqrtf(var + 1e-5f);
        }
    }
    __syncthreads();

    {
        float qa[8];
#pragma unroll
        for (int i = 0; i < 8; i++) qa[i] = 0.f;
        for (int c0 = 0; c0 < 256; c0 += 4) {
            float w0 = WqT[(size_t)(c0 + 0) * 256 + t];
            float w1 = WqT[(size_t)(c0 + 1) * 256 + t];
            float w2 = WqT[(size_t)(c0 + 2) * 256 + t];
            float w3 = WqT[(size_t)(c0 + 3) * 256 + t];
#pragma unroll
            for (int i = 0; i < 8; i++) {
                float4 sv = *(const float4*)&sln[i][c0];
                qa[i] += sv.x * w0 + sv.y * w1 + sv.z * w2 + sv.w * w3;
            }
        }
        float s1 = S1q[t], s2v = S2q[t];
#pragma unroll
        for (int i = 0; i < 8; i++) {
            float qv = rr[i] * qa[i] - rr[i] * rm[i] * s1 + s2v;
            qs[i][t] = qv * SCALE_F;
        }
    }
    __syncthreads();

    float rsa = 0.f;
#pragma unroll 1
    for (int jj = 0; jj < 16; jj++) {
        int jl = w + jj * 8;
        int j = jc * 128 + jl;
        const float* krow = kv + ((size_t)b * NTOK + j) * 512;
        float kr[8];
#pragma unroll
        for (int u = 0; u < 8; u++) kr[u] = krow[u * 32 + lane];
        float dv[8];
#pragma unroll
        for (int i = 0; i < 8; i++) {
            float p = 0.f;
#pragma unroll
            for (int u = 0; u < 8; u++) p += qs[i][u * 32 + lane] * kr[u];
            dv[i] = warp_sum(p);
        }
        float mx = dv[0];
#pragma unroll
        for (int i = 1; i < 8; i++) mx = fmaxf(mx, dv[i]);
        float se = 0.f, ev[8];
#pragma unroll
        for (int i = 0; i < 8; i++) { ev[i] = __expf(dv[i] - mx); se += ev[i]; }
        float inv = 1.0f / se;
        float my = 0.f;
#pragma unroll
        for (int i = 0; i < 8; i++) {
            float a = ev[i] * inv + EPS_F;
            if (lane == i) my = a;
        }
        if (lane < 8) { attn_s[jl][lane] = my; rsa += my; }
    }
    if (lane < 8) rswarp[w][lane] = rsa;
    __syncthreads();

    {
        float uacc[8];
#pragma unroll
        for (int i = 0; i < 8; i++) uacc[i] = 0.f;
        const float* vbase = kv + ((size_t)b * NTOK + jc * 128) * 512 + 256 + t;
#pragma unroll 2
        for (int jl = 0; jl < 128; jl++) {
            float va = vbase[(size_t)jl * 512];
#pragma unroll
            for (int i = 0; i < 8; i++) uacc[i] += attn_s[jl][i] * va;
        }
#pragma unroll
        for (int i = 0; i < 8; i++)
            updp[((size_t)jc * SROWS + b * 8 + i) * 256 + t] = uacc[i];
        if (t < 8) {
            float r = 0.f;
#pragma unroll
            for (int ww = 0; ww < 8; ww++) r += rswarp[ww][t];
            rsp[jc * SROWS + b * 8 + t] = r;
        }
    }
}

// u = (sum_p updp) / (sum_p rowsum)
__global__ void reduce_u_kernel(const float* __restrict__ updp, const float* __restrict__ rsp,
                                float* __restrict__ u) {
    int idx4 = blockIdx.x * blockDim.x + threadIdx.x;
    int row = idx4 >> 6;
    float rs = 0.f;
#pragma unroll
    for (int p = 0; p < NCHUNK; p++) rs += rsp[p * SROWS + row];
    float inv = 1.0f / rs;
    float4 a = make_float4(0.f, 0.f, 0.f, 0.f);
#pragma unroll
    for (int p = 0; p < NCHUNK; p++) {
        float4 v = *(const float4*)(updp + (size_t)p * SROWS * 256 + (size_t)idx4 * 4);
        a.x += v.x; a.y += v.y; a.z += v.z; a.w += v.w;
    }
    a.x *= inv; a.y *= inv; a.z *= inv; a.w *= inv;
    *(float4*)(u + (size_t)idx4 * 4) = a;
}

// ---------------------------------------------------------------------------
// fused GRU: gi=u@wih^T, gh=h@whh^T (3 gates each), nonlinearity, out.
// ---------------------------------------------------------------------------
__global__ __launch_bounds__(256) void gru_fused_kernel(
    const float* __restrict__ u, const float* __restrict__ slots,
    const float* __restrict__ wih, const float* __restrict__ whh,
    const float* __restrict__ bih, const float* __restrict__ bhh,
    float* __restrict__ out) {
    __shared__ float Au[32][36], Ah[32][36];
    __shared__ float Bg[6][32][36];
    int t = threadIdx.x;
    int bm = blockIdx.y * 32, bn = blockIdx.x * 32;
    float acc[6][2][2];
#pragma unroll
    for (int gb = 0; gb < 6; gb++)
#pragma unroll
        for (int i = 0; i < 2; i++)
#pragma unroll
            for (int j = 0; j < 2; j++) acc[gb][i][j] = 0.f;
    int tr = t >> 4, tc = t & 15;
    int lm = t >> 3, lk = (t & 7) * 4;

    float4 pu, ph, pw[6];
    pu = *(const float4*)(u + (size_t)(bm + lm) * 256 + lk);
    ph = *(const float4*)(slots + (size_t)(bm + lm) * 256 + lk);
#pragma unroll
    for (int gb = 0; gb < 6; gb++) {
        const float* W = (gb < 3) ? wih : whh;
        pw[gb] = *(const float4*)(W + (size_t)(bn + lm + (gb % 3) * 256) * 256 + lk);
    }
    for (int it = 0; it < 8; it++) {
        __syncthreads();
        Au[lm][lk + 0] = pu.x; Au[lm][lk + 1] = pu.y; Au[lm][lk + 2] = pu.z; Au[lm][lk + 3] = pu.w;
        Ah[lm][lk + 0] = ph.x; Ah[lm][lk + 1] = ph.y; Ah[lm][lk + 2] = ph.z; Ah[lm][lk + 3] = ph.w;
#pragma unroll
        for (int gb = 0; gb < 6; gb++) {
            Bg[gb][lm][lk + 0] = pw[gb].x; Bg[gb][lm][lk + 1] = pw[gb].y;
            Bg[gb][lm][lk + 2] = pw[gb].z; Bg[gb][lm][lk + 3] = pw[gb].w;
        }
        __syncthreads();
        if (it < 7) {
            int c = (it + 1) * 32 + lk;
            pu = *(const float4*)(u + (size_t)(bm + lm) * 256 + c);
            ph = *(const float4*)(slots + (size_t)(bm + lm) * 256 + c);
#pragma unroll
            for (int gb = 0; gb < 6; gb++) {
                const float* W = (gb < 3) ? wih : whh;
                pw[gb] = *(const float4*)(W + (size_t)(bn + lm + (gb % 3) * 256) * 256 + c);
            }
        }
#pragma unroll
        for (int kk = 0; kk < 32; kk++) {
            float a0u = Au[tr * 2][kk], a1u = Au[tr * 2 + 1][kk];
            float a0h = Ah[tr * 2][kk], a1h = Ah[tr * 2 + 1][kk];
#pragma unroll
            for (int gb = 0; gb < 6; gb++) {
                float b0 = Bg[gb][tc * 2][kk], b1 = Bg[gb][tc * 2 + 1][kk];
                float x0 = (gb < 3) ? a0u : a0h;
                float x1 = (gb < 3) ? a1u : a1h;
                acc[gb][0][0] += x0 * b0; acc[gb][0][1] += x0 * b1;
                acc[gb][1][0] += x1 * b0; acc[gb][1][1] += x1 * b1;
            }
        }
    }
#pragma unroll
    for (int i = 0; i < 2; i++)
#pragma unroll
        for (int j = 0; j < 2; j++) {
            int row = bm + tr * 2 + i, col = bn + tc * 2 + j;
            float ir = acc[0][i][j] + bih[col];
            float iz = acc[1][i][j] + bih[col + 256];
            float in_ = acc[2][i][j] + bih[col + 512];
            float hr = acc[3][i][j] + bhh[col];
            float hz = acc[4][i][j] + bhh[col + 256];
            float hn = acc[5][i][j] + bhh[col + 512];
            float r = sigmoidf_(ir + hr);
            float z = sigmoidf_(iz + hz);
            float nn = tanhf(in_ + r * hn);
            float h = slots[(size_t)row * 256 + col];
            out[(size_t)row * 256 + col] = (1.0f - z) * nn + z * h;
        }
}

// ---------------------------------------------------------------------------
// small GEMM with register prefetch: C = [LN-fold](A) @ B^T (+bias, relu, +add)
// ---------------------------------------------------------------------------
template<bool EPI_LN, bool RELU, bool ADDOUT>
__global__ __launch_bounds__(256) void gemm_small_kernel(
    const float* __restrict__ A, const float* __restrict__ B,
    const float* __restrict__ S1, const float* __restrict__ S2,
    const float* __restrict__ bias, const float* __restrict__ addsrc,
    float* __restrict__ C, int M, int N, int K) {
    __shared__ float As[32][68];
    __shared__ float Bs[32][68];
    __shared__ float rowm[64], rowr[64];
    int t = threadIdx.x;
    int bm = blockIdx.y * 64, bn = blockIdx.x * 64;
    int tr = t >> 4, tc = t & 15;
    float acc[4][4];
#pragma unroll
    for (int i = 0; i < 4; i++)
#pragma unroll
        for (int j = 0; j < 4; j++) acc[i][j] = 0.f;
    int lm = t >> 3, lk = (t & 7) * 4;

    float4 ap0, ap1, bp0, bp1;
    float sA[2] = {0.f, 0.f}, s2A[2] = {0.f, 0.f};
    ap0 = *(const float4*)(A + (size_t)(bm + lm) * K + lk);
    ap1 = *(const float4*)(A + (size_t)(bm + lm + 32) * K + lk);
    bp0 = *(const float4*)(B + (size_t)(bn + lm) * K + lk);
    bp1 = *(const float4*)(B + (size_t)(bn + lm + 32) * K + lk);
    int iters = K >> 5;
    for (int it = 0; it < iters; it++) {
        if (EPI_LN) {
            sA[0] += ap0.x + ap0.y + ap0.z + ap0.w;
            s2A[0] += ap0.x * ap0.x + ap0.y * ap0.y + ap0.z * ap0.z + ap0.w * ap0.w;
            sA[1] += ap1.x + ap1.y + ap1.z + ap1.w;
            s2A[1] += ap1.x * ap1.x + ap1.y * ap1.y + ap1.z * ap1.z + ap1.w * ap1.w;
        }
        __syncthreads();
        As[lk + 0][lm] = ap0.x; As[lk + 1][lm] = ap0.y; As[lk + 2][lm] = ap0.z; As[lk + 3][lm] = ap0.w;
        As[lk + 0][lm + 32] = ap1.x; As[lk + 1][lm + 32] = ap1.y; As[lk + 2][lm + 32] = ap1.z; As[lk + 3][lm + 32] = ap1.w;
        Bs[lk + 0][lm] = bp0.x; Bs[lk + 1][lm] = bp0.y; Bs[lk + 2][lm] = bp0.z; Bs[lk + 3][lm] = bp0.w;
        Bs[lk + 0][lm + 32] = bp1.x; Bs[lk + 1][lm + 32] = bp1.y; Bs[lk + 2][lm + 32] = bp1.z; Bs[lk + 3][lm + 32] = bp1.w;
        __syncthreads();
        if (it + 1 < iters) {
            int c = (it + 1) * 32 + lk;
            ap0 = *(const float4*)(A + (size_t)(bm + lm) * K + c);
            ap1 = *(const float4*)(A + (size_t)(bm + lm + 32) * K + c);
            bp0 = *(const float4*)(B + (size_t)(bn + lm) * K + c);
            bp1 = *(const float4*)(B + (size_t)(bn + lm + 32) * K + c);
        }
#pragma unroll
        for (int kk = 0; kk < 32; kk++) {
            float4 a4 = *(float4*)&As[kk][tr * 4];
            float4 b4 = *(float4*)&Bs[kk][tc * 4];
            float a[4] = {a4.x, a4.y, a4.z, a4.w};
            float b[4] = {b4.x, b4.y, b4.z, b4.w};
#pragma unroll
            for (int i = 0; i < 4; i++)
#pragma unroll
                for (int j = 0; j < 4; j++) acc[i][j] += a[i] * b[j];
        }
    }
    if (EPI_LN) {
#pragma unroll
        for (int r = 0; r < 2; r++) {
            float s = grp8_sum(sA[r]);
            float s2 = grp8_sum(s2A[r]);
            if ((t & 7) == 0) {
                float m = s / (float)K;
                float var = s2 / (float)K - m * m;
                rowm[r * 32 + lm] = m;
                rowr[r * 32 + lm] = rsqrtf(var + 1e-5f);
            }
        }
        __syncthreads();
    }
#pragma unroll
    for (int i = 0; i < 4; i++)
#pragma unroll
        for (int j = 0; j < 4; j++) {
            int lr = tr * 4 + i;
            int row = bm + lr, col = bn + tc * 4 + j;
            float v = acc[i][j];
            if (EPI_LN) {
                float m = rowm[lr], rs = rowr[lr];
                v = rs * v - rs * m * S1[col] + S2[col];
            }
            if (bias) v += bias[col];
            if (RELU) v = fmaxf(v, 0.f);
            if (ADDOUT) v += addsrc[(size_t)row * N + col];
            C[(size_t)row * N + col] = v;
        }
}

extern "C" void kernel_launch(void* const* d_in, const int* in_sizes, int n_in,
                              void* d_out, int out_size) {
    const float* inputs    = (const float*)d_in[0];
    const float* noise     = (const float*)d_in[1];
    const float* slots_mu  = (const float*)d_in[2];
    const float* slots_ls  = (const float*)d_in[3];
    const float* Wq        = (const float*)d_in[4];
    const float* Wk        = (const float*)d_in[5];
    const float* Wv        = (const float*)d_in[6];
    const float* gru_wih   = (const float*)d_in[7];
    const float* gru_whh   = (const float*)d_in[8];
    const float* gru_bih   = (const float*)d_in[9];
    const float* gru_bhh   = (const float*)d_in[10];
    const float* mlp_w1    = (const float*)d_in[11];
    const float* mlp_b1    = (const float*)d_in[12];
    const float* mlp_w2    = (const float*)d_in[13];
    const float* mlp_b2    = (const float*)d_in[14];
    const float* ln_in_g   = (const float*)d_in[15];
    const float* ln_in_b   = (const float*)d_in[16];
    const float* ln_s_g    = (const float*)d_in[17];
    const float* ln_s_b    = (const float*)d_in[18];
    const float* ln_ff_g   = (const float*)d_in[19];
    const float* ln_ff_b   = (const float*)d_in[20];

    float* S = nullptr;
    cudaGetSymbolAddress((void**)&S, g_scratch);
    __nv_bfloat16* wb = nullptr;
    cudaGetSymbolAddress((void**)&wb, g_wb);
    float* kv    = S + OFF_KV;
    float* slots = S + OFF_SLOTS;
    float* gbuf  = S + OFF_GBUF;
    float* ubuf  = S + OFF_U;
    float* h1    = S + OFF_H1;
    float* updp  = S + OFF_UPDP;
    float* rsp   = S + OFF_RSP;
    float* S1kv  = S + OFF_S1KV;
    float* S2kv  = S + OFF_S2KV;
    float* WqT   = S + OFF_WQT;
    float* S1q   = S + OFF_S1Q;
    float* S2q   = S + OFF_S2Q;
    float* W1p   = S + OFF_W1P;
    float* S1m   = S + OFF_S1M;
    float* S2m   = S + OFF_S2M;

    prep_kv_kernel<<<64, 256>>>(Wk, Wv, ln_in_g, ln_in_b, wb, S1kv, S2kv);    // 0
    prep_q_kernel<<<32, 256>>>(Wq, ln_s_g, ln_s_b, WqT, S1q, S2q);            // 1
    prep_m1_kernel<<<128, 256>>>(mlp_w1, ln_ff_g, ln_ff_b, W1p, S1m, S2m);    // 2
    kv_mma_kernel<<<dim3(4, 256), 256>>>(inputs, wb, S1kv, S2kv, kv);         // 3 (profiled)
    init_slots_kernel<<<256, 256>>>(slots_mu, slots_ls, noise, slots);        // 4

    for (int it = 0; it < ITERS; it++) {
        attn_fused_kernel<<<dim3(32, NCHUNK), 256>>>(slots, WqT, S1q, S2q, kv, updp, rsp);
        reduce_u_kernel<<<64, 256>>>(updp, rsp, ubuf);
        gru_fused_kernel<<<dim3(8, 8), 256>>>(ubuf, slots, gru_wih, gru_whh, gru_bih, gru_bhh, gbuf);
        gemm_small_kernel<true, true, false><<<dim3(16, 4), 256>>>(
            gbuf, W1p, S1m, S2m, mlp_b1, nullptr, h1, 256, 1024, 256);
        float* outp = (it == ITERS - 1) ? (float*)d_out : slots;
        gemm_small_kernel<false, false, true><<<dim3(4, 4), 256>>>(
            h1, mlp_w2, nullptr, nullptr, mlp_b2, gbuf, outp, 256, 256, 1024);
    }
}

// round 11
// speedup vs baseline: 1.5296x; 1.5296x over previous
#include <cuda_runtime.h>
#include <cuda_bf16.h>
#include <math.h>
#include <cstdint>

// ---------------------------------------------------------------------------
// SlotAttention: b=32, n=1024, c=256, d=256, S=8 slots, 3 iters.
// KV: bf16 m16n8k16 mma.sync (tcgen05 rejected by compute_103 PTX stage).
// Per-iter chain: 16-row-tile GEMMs, 128 blocks/phase, q hoisted out of attn,
// updp reduction folded into GRU. 15 launches total.
// ---------------------------------------------------------------------------
#define NTOK 1024
#define ITERS 3
#define TOKROWS 32768
#define SROWS 256
#define SCALE_F 0.0625f
#define EPS_F 1e-8f
#define NCHUNK 8

// scratch arena (floats)
#define OFF_KV     0                                  // 32768*512
#define OFF_SLOTS  (OFF_KV + TOKROWS*512)             // 256*256
#define OFF_GBUF   (OFF_SLOTS + SROWS*256)
#define OFF_Q      (OFF_GBUF + SROWS*256)
#define OFF_H1     (OFF_Q + SROWS*256)                // 256*1024
#define OFF_UPDP   (OFF_H1 + SROWS*1024)              // 8*256*256
#define OFF_RSP    (OFF_UPDP + NCHUNK*SROWS*256)      // 8*256
#define OFF_S1KV   (OFF_RSP + NCHUNK*SROWS)           // 512
#define OFF_S2KV   (OFF_S1KV + 512)
#define OFF_WQP    (OFF_S2KV + 512)                   // 256*256 row-major
#define OFF_S1Q    (OFF_WQP + 256*256)
#define OFF_S2Q    (OFF_S1Q + 256)
#define OFF_W1P    (OFF_S2Q + 256)                    // 1024*256
#define OFF_S1M    (OFF_W1P + 1024*256)
#define OFF_S2M    (OFF_S1M + 1024)
#define SCRATCH_FLOATS (OFF_S2M + 1024)

__device__ float g_scratch[SCRATCH_FLOATS];
__device__ __align__(16) __nv_bfloat16 g_wb[512 * 256];

__device__ __forceinline__ float warp_sum(float v) {
#pragma unroll
    for (int o = 16; o > 0; o >>= 1) v += __shfl_xor_sync(0xffffffffu, v, o);
    return v;
}
__device__ __forceinline__ float grp8_sum(float v) {
    v += __shfl_xor_sync(0xffffffffu, v, 4);
    v += __shfl_xor_sync(0xffffffffu, v, 2);
    v += __shfl_xor_sync(0xffffffffu, v, 1);
    return v;
}
__device__ __forceinline__ float sigmoidf_(float x) { return 1.0f / (1.0f + __expf(-x)); }

__device__ __forceinline__ void mma16(float* d, const unsigned* a, const unsigned* b) {
    asm volatile("mma.sync.aligned.m16n8k16.row.col.f32.bf16.bf16.f32 "
        "{%0,%1,%2,%3}, {%4,%5,%6,%7}, {%8,%9}, {%0,%1,%2,%3};"
        : "+f"(d[0]), "+f"(d[1]), "+f"(d[2]), "+f"(d[3])
        : "r"(a[0]), "r"(a[1]), "r"(a[2]), "r"(a[3]), "r"(b[0]), "r"(b[1]));
}

// ---------------------------------------------------------------------------
// setup: all weight preps + slot init in ONE kernel (grid 480).
//  blocks [0,64):   bf16 [Wk;Wv] + S1kv/S2kv
//  blocks [64,96):  W'q row-major fp32 + S1q/S2q
//  blocks [96,224): W'1 row-major fp32 + S1m/S2m
//  blocks [224,480): slots = mu + exp(ls)*noise
// ---------------------------------------------------------------------------
__global__ void setup_kernel(
    const float* __restrict__ Wk, const float* __restrict__ Wv,
    const float* __restrict__ ln_in_g, const float* __restrict__ ln_in_b,
    __nv_bfloat16* __restrict__ wb, float* __restrict__ S1kv, float* __restrict__ S2kv,
    const float* __restrict__ Wq, const float* __restrict__ ln_s_g, const float* __restrict__ ln_s_b,
    float* __restrict__ Wqp, float* __restrict__ S1q, float* __restrict__ S2q,
    const float* __restrict__ W1, const float* __restrict__ ln_ff_g, const float* __restrict__ ln_ff_b,
    float* __restrict__ W1p, float* __restrict__ S1m, float* __restrict__ S2m,
    const float* __restrict__ mu, const float* __restrict__ ls,
    const float* __restrict__ noise, float* __restrict__ slots) {
    int blk = blockIdx.x;
    int w = threadIdx.x >> 5, lane = threadIdx.x & 31;
    if (blk < 64) {
        int n = blk * 8 + w;
        const float* src = (n < 256) ? Wk + (size_t)n * 256 : Wv + (size_t)(n - 256) * 256;
        float s1 = 0.f, s2 = 0.f;
#pragma unroll
        for (int u = 0; u < 8; u++) {
            int c = u * 32 + lane;
            __nv_bfloat16 bf = __float2bfloat16(src[c] * ln_in_g[c]);
            wb[(size_t)n * 256 + c] = bf;
            s1 += __bfloat162float(bf);
            s2 += src[c] * ln_in_b[c];
        }
        s1 = warp_sum(s1); s2 = warp_sum(s2);
        if (lane == 0) { S1kv[n] = s1; S2kv[n] = s2; }
    } else if (blk < 96) {
        int n = (blk - 64) * 8 + w;
        float s1 = 0.f, s2 = 0.f;
#pragma unroll
        for (int u = 0; u < 8; u++) {
            int c = u * 32 + lane;
            float wv = Wq[(size_t)n * 256 + c] * ln_s_g[c];
            Wqp[(size_t)n * 256 + c] = wv;
            s1 += wv;
            s2 += Wq[(size_t)n * 256 + c] * ln_s_b[c];
        }
        s1 = warp_sum(s1); s2 = warp_sum(s2);
        if (lane == 0) { S1q[n] = s1; S2q[n] = s2; }
    } else if (blk < 224) {
        int n = (blk - 96) * 8 + w;
        float s1 = 0.f, s2 = 0.f;
#pragma unroll
        for (int u = 0; u < 8; u++) {
            int c = u * 32 + lane;
            float wv = W1[(size_t)n * 256 + c] * ln_ff_g[c];
            W1p[(size_t)n * 256 + c] = wv;
            s1 += wv;
            s2 += W1[(size_t)n * 256 + c] * ln_ff_b[c];
        }
        s1 = warp_sum(s1); s2 = warp_sum(s2);
        if (lane == 0) { S1m[n] = s1; S2m[n] = s2; }
    } else {
        int idx = (blk - 224) * 256 + threadIdx.x;
        int d = idx & 255;
        slots[idx] = mu[d] + __expf(ls[d]) * noise[idx];
    }
}

// ---------------------------------------------------------------------------
// KV GEMM (unchanged from R10, 74.7us measured): bf16 m16n8k16, LN-fold.
// ---------------------------------------------------------------------------
__global__ __launch_bounds__(256) void kv_mma_kernel(
    const float* __restrict__ x, const __nv_bfloat16* __restrict__ wb,
    const float* __restrict__ S1, const float* __restrict__ S2,
    float* __restrict__ C) {
    __shared__ uint32_t As[128][20];
    __shared__ uint32_t Bs[128][20];
    __shared__ float rowm[128], rowr[128];
    int t = threadIdx.x;
    int bm = blockIdx.y * 128, bn = blockIdx.x * 128;
    int w = t >> 5, lane = t & 31;
    int m0 = (w >> 2) * 64, n0 = (w & 3) * 32;
    int g = lane >> 2, tig = lane & 3;
    float acc[4][4][4];
#pragma unroll
    for (int a = 0; a < 4; a++)
#pragma unroll
        for (int bq = 0; bq < 4; bq++)
#pragma unroll
            for (int c = 0; c < 4; c++) acc[a][bq][c] = 0.f;

    int lm = t >> 3;
    int lkf = (t & 7) * 4;
    int lku = (t & 7) * 2;

    float4 ar[4]; uint2 br[4];
    float sA[4] = {0.f, 0.f, 0.f, 0.f}, s2A[4] = {0.f, 0.f, 0.f, 0.f};
#pragma unroll
    for (int r = 0; r < 4; r++) {
        ar[r] = *(const float4*)(x + (size_t)(bm + r * 32 + lm) * 256 + lkf);
        br[r] = *(const uint2*)(wb + (size_t)(bn + r * 32 + lm) * 256 + lkf);
    }
    for (int it = 0; it < 8; it++) {
#pragma unroll
        for (int r = 0; r < 4; r++) {
            sA[r] += ar[r].x + ar[r].y + ar[r].z + ar[r].w;
            s2A[r] += ar[r].x * ar[r].x + ar[r].y * ar[r].y + ar[r].z * ar[r].z + ar[r].w * ar[r].w;
        }
        __syncthreads();
#pragma unroll
        for (int r = 0; r < 4; r++) {
            int m = r * 32 + lm;
            __nv_bfloat162 p0 = __floats2bfloat162_rn(ar[r].x, ar[r].y);
            __nv_bfloat162 p1 = __floats2bfloat162_rn(ar[r].z, ar[r].w);
            As[m][lku + 0] = *(uint32_t*)&p0;
            As[m][lku + 1] = *(uint32_t*)&p1;
            Bs[m][lku + 0] = br[r].x;
            Bs[m][lku + 1] = br[r].y;
        }
        __syncthreads();
        if (it < 7) {
            int c = (it + 1) * 32 + lkf;
#pragma unroll
            for (int r = 0; r < 4; r++) {
                ar[r] = *(const float4*)(x + (size_t)(bm + r * 32 + lm) * 256 + c);
                br[r] = *(const uint2*)(wb + (size_t)(bn + r * 32 + lm) * 256 + c);
            }
        }
#pragma unroll
        for (int ks = 0; ks < 2; ks++) {
            unsigned a[4][4], b[4][2];
#pragma unroll
            for (int mt = 0; mt < 4; mt++) {
                int mr = m0 + mt * 16 + g;
                a[mt][0] = As[mr][ks * 8 + tig];
                a[mt][1] = As[mr + 8][ks * 8 + tig];
                a[mt][2] = As[mr][ks * 8 + tig + 4];
                a[mt][3] = As[mr + 8][ks * 8 + tig + 4];
            }
#pragma unroll
            for (int nt = 0; nt < 4; nt++) {
                int nr = n0 + nt * 8 + g;
                b[nt][0] = Bs[nr][ks * 8 + tig];
                b[nt][1] = Bs[nr][ks * 8 + tig + 4];
            }
#pragma unroll
            for (int mt = 0; mt < 4; mt++)
#pragma unroll
                for (int nt = 0; nt < 4; nt++)
                    mma16(acc[mt][nt], a[mt], b[nt]);
        }
    }
#pragma unroll
    for (int r = 0; r < 4; r++) {
        float s = grp8_sum(sA[r]);
        float s2 = grp8_sum(s2A[r]);
        if ((t & 7) == 0) {
            float m = s * (1.0f / 256.0f);
            float var = s2 * (1.0f / 256.0f) - m * m;
            rowm[r * 32 + lm] = m;
            rowr[r * 32 + lm] = rsqrtf(var + 1e-5f);
        }
    }
    __syncthreads();
#pragma unroll
    for (int mt = 0; mt < 4; mt++)
#pragma unroll
        for (int nt = 0; nt < 4; nt++) {
            int lr = m0 + mt * 16 + g;
            int col = bn + n0 + nt * 8 + tig * 2;
            float s1a = S1[col], s1b = S1[col + 1], s2a = S2[col], s2b = S2[col + 1];
            float m0v = rowm[lr], r0v = rowr[lr];
            float m1v = rowm[lr + 8], r1v = rowr[lr + 8];
            float2 o0 = make_float2(r0v * acc[mt][nt][0] - r0v * m0v * s1a + s2a,
                                    r0v * acc[mt][nt][1] - r0v * m0v * s1b + s2b);
            float2 o1 = make_float2(r1v * acc[mt][nt][2] - r1v * m1v * s1a + s2a,
                                    r1v * acc[mt][nt][3] - r1v * m1v * s1b + s2b);
            *(float2*)(C + (size_t)(bm + lr) * 512 + col) = o0;
            *(float2*)(C + (size_t)(bm + lr + 8) * 512 + col) = o1;
        }
}

// ---------------------------------------------------------------------------
// gemm16: 16-row x NC-col tiles, 256 threads, register-prefetched BK=32.
// C[M,N] = [LNfold](A[M,K]) @ B[N,K]^T (+bias,+relu,+qscale,+add).
// grid (N/NC, M/16). thread: rows (t>>5, t>>5+8), cols (t&31)+32c.
// ---------------------------------------------------------------------------
template<int NC, bool LNF, bool RELU, bool ADDOUT, bool QSC>
__global__ __launch_bounds__(256) void gemm16_kernel(
    const float* __restrict__ A, const float* __restrict__ B,
    const float* __restrict__ S1, const float* __restrict__ S2,
    const float* __restrict__ bias, const float* __restrict__ addsrc,
    float* __restrict__ C, int N, int K) {
    constexpr int CPT = NC / 32;
    __shared__ float As[16][34];
    __shared__ float Bs[NC][34];
    __shared__ float rowm[16], rowr[16];
    int t = threadIdx.x;
    int bm = blockIdx.y * 16, bn = blockIdx.x * NC;
    if (LNF) {
        int w = t >> 5, lane = t & 31;
#pragma unroll
        for (int rr = 0; rr < 2; rr++) {
            int row = w * 2 + rr;
            const float* p = A + (size_t)(bm + row) * 256;
            float s = 0.f, s2 = 0.f;
#pragma unroll
            for (int u = 0; u < 8; u++) { float v = p[lane + u * 32]; s += v; s2 += v * v; }
            s = warp_sum(s); s2 = warp_sum(s2);
            if (lane == 0) {
                float m = s * (1.0f / 256.0f);
                float var = s2 * (1.0f / 256.0f) - m * m;
                rowm[row] = m; rowr[row] = rsqrtf(var + 1e-5f);
            }
        }
    }
    int ar = t >> 4, ak = (t & 15) * 2;
    int brr = t >> 3, bk = (t & 7) * 4;
    int tr = t >> 5, tc = t & 31;
    float acc[2][CPT];
#pragma unroll
    for (int r = 0; r < 2; r++)
#pragma unroll
        for (int c = 0; c < CPT; c++) acc[r][c] = 0.f;

    float2 pa = *(const float2*)(A + (size_t)(bm + ar) * K + ak);
    float4 pb[CPT];
#pragma unroll
    for (int c = 0; c < CPT; c++)
        pb[c] = *(const float4*)(B + (size_t)(bn + c * 32 + brr) * K + bk);

    int KT = K >> 5;
    for (int kt = 0; kt < KT; kt++) {
        __syncthreads();
        As[ar][ak] = pa.x; As[ar][ak + 1] = pa.y;
#pragma unroll
        for (int c = 0; c < CPT; c++) {
            Bs[c * 32 + brr][bk + 0] = pb[c].x; Bs[c * 32 + brr][bk + 1] = pb[c].y;
            Bs[c * 32 + brr][bk + 2] = pb[c].z; Bs[c * 32 + brr][bk + 3] = pb[c].w;
        }
        __syncthreads();
        if (kt + 1 < KT) {
            int k0 = (kt + 1) * 32;
            pa = *(const float2*)(A + (size_t)(bm + ar) * K + k0 + ak);
#pragma unroll
            for (int c = 0; c < CPT; c++)
                pb[c] = *(const float4*)(B + (size_t)(bn + c * 32 + brr) * K + k0 + bk);
        }
#pragma unroll
        for (int kk = 0; kk < 32; kk += 2) {
            float2 a0 = *(const float2*)&As[tr][kk];
            float2 a1 = *(const float2*)&As[tr + 8][kk];
#pragma unroll
            for (int c = 0; c < CPT; c++) {
                float2 b2 = *(const float2*)&Bs[tc + c * 32][kk];
                acc[0][c] += a0.x * b2.x + a0.y * b2.y;
                acc[1][c] += a1.x * b2.x + a1.y * b2.y;
            }
        }
    }
#pragma unroll
    for (int r = 0; r < 2; r++) {
        int lr = tr + r * 8;
        int row = bm + lr;
#pragma unroll
        for (int c = 0; c < CPT; c++) {
            int col = bn + c * 32 + tc;
            float v = acc[r][c];
            if (LNF) { float m = rowm[lr], rs = rowr[lr]; v = rs * v - rs * m * S1[col] + S2[col]; }
            if (bias) v += bias[col];
            if (RELU) v = fmaxf(v, 0.f);
            if (QSC) v *= SCALE_F;
            if (ADDOUT) v += addsrc[(size_t)row * N + col];
            C[(size_t)row * N + col] = v;
        }
    }
}

// ---------------------------------------------------------------------------
// attention (q precomputed): dots + softmax over slots + updates partials.
// grid (32 batches, 8 j-chunks of 128).
// ---------------------------------------------------------------------------
__global__ __launch_bounds__(256) void attn2_kernel(
    const float* __restrict__ qbuf, const float* __restrict__ kv,
    float* __restrict__ updp, float* __restrict__ rsp) {
    __shared__ float qs[8][256];
    __shared__ float attn_s[128][9];
    __shared__ float rswarp[8][8];
    int b = blockIdx.x, jc = blockIdx.y;
    int t = threadIdx.x, w = t >> 5, lane = t & 31;

#pragma unroll
    for (int u = 0; u < 8; u++)
        qs[u][t] = qbuf[(size_t)(b * 8 + u) * 256 + t];
    __syncthreads();

    float rsa = 0.f;
#pragma unroll 1
    for (int jj = 0; jj < 16; jj++) {
        int jl = w + jj * 8;
        int j = jc * 128 + jl;
        const float* krow = kv + ((size_t)b * NTOK + j) * 512;
        float kr[8];
#pragma unroll
        for (int u = 0; u < 8; u++) kr[u] = krow[u * 32 + lane];
        float dv[8];
#pragma unroll
        for (int i = 0; i < 8; i++) {
            float p = 0.f;
#pragma unroll
            for (int u = 0; u < 8; u++) p += qs[i][u * 32 + lane] * kr[u];
            dv[i] = warp_sum(p);
        }
        float mx = dv[0];
#pragma unroll
        for (int i = 1; i < 8; i++) mx = fmaxf(mx, dv[i]);
        float se = 0.f, ev[8];
#pragma unroll
        for (int i = 0; i < 8; i++) { ev[i] = __expf(dv[i] - mx); se += ev[i]; }
        float inv = 1.0f / se;
        float my = 0.f;
#pragma unroll
        for (int i = 0; i < 8; i++) {
            float a = ev[i] * inv + EPS_F;
            if (lane == i) my = a;
        }
        if (lane < 8) { attn_s[jl][lane] = my; rsa += my; }
    }
    if (lane < 8) rswarp[w][lane] = rsa;
    __syncthreads();

    {
        float uacc[8];
#pragma unroll
        for (int i = 0; i < 8; i++) uacc[i] = 0.f;
        const float* vbase = kv + ((size_t)b * NTOK + jc * 128) * 512 + 256 + t;
#pragma unroll 2
        for (int jl = 0; jl < 128; jl++) {
            float va = vbase[(size_t)jl * 512];
#pragma unroll
            for (int i = 0; i < 8; i++) uacc[i] += attn_s[jl][i] * va;
        }
#pragma unroll
        for (int i = 0; i < 8; i++)
            updp[((size_t)jc * SROWS + b * 8 + i) * 256 + t] = uacc[i];
        if (t < 8) {
            float r = 0.f;
#pragma unroll
            for (int ww = 0; ww < 8; ww++) r += rswarp[ww][t];
            rsp[jc * SROWS + b * 8 + t] = r;
        }
    }
}

// ---------------------------------------------------------------------------
// GRU, 16x32 units, updp reduction inline. grid (8, 16) = 128 blocks.
// ---------------------------------------------------------------------------
__global__ __launch_bounds__(256) void gru16_kernel(
    const float* __restrict__ updp, const float* __restrict__ rsp,
    const float* __restrict__ slots,
    const float* __restrict__ wih, const float* __restrict__ whh,
    const float* __restrict__ bih, const float* __restrict__ bhh,
    float* __restrict__ out) {
    __shared__ float Au[16][34], Ah[16][34];
    __shared__ float Bg[6][32][34];
    __shared__ float invrs[16];
    int t = threadIdx.x;
    int bm = blockIdx.y * 16, bn = blockIdx.x * 32;
    if (t < 16) {
        float rs = 0.f;
#pragma unroll
        for (int p = 0; p < NCHUNK; p++) rs += rsp[p * 256 + bm + t];
        invrs[t] = 1.0f / rs;
    }
    int ar = t >> 4, ak = (t & 15) * 2;
    int brr = t >> 3, bk = (t & 7) * 4;
    int tr = t >> 5, tc = t & 31;
    float acc[6][2];
#pragma unroll
    for (int g = 0; g < 6; g++) { acc[g][0] = 0.f; acc[g][1] = 0.f; }

    for (int kt = 0; kt < 8; kt++) {
        int k0 = kt * 32;
        __syncthreads();
        {
            size_t base = (size_t)(bm + ar) * 256 + k0 + ak;
            float sx = 0.f, sy = 0.f;
#pragma unroll
            for (int p = 0; p < NCHUNK; p++) {
                float2 v = *(const float2*)(updp + (size_t)p * 65536 + base);
                sx += v.x; sy += v.y;
            }
            float iv = invrs[ar];
            Au[ar][ak] = sx * iv; Au[ar][ak + 1] = sy * iv;
            float2 h2 = *(const float2*)(slots + base);
            Ah[ar][ak] = h2.x; Ah[ar][ak + 1] = h2.y;
#pragma unroll
            for (int g = 0; g < 6; g++) {
                const float* W = (g < 3) ? wih : whh;
                float4 w4 = *(const float4*)(W + (size_t)((g % 3) * 256 + bn + brr) * 256 + k0 + bk);
                Bg[g][brr][bk + 0] = w4.x; Bg[g][brr][bk + 1] = w4.y;
                Bg[g][brr][bk + 2] = w4.z; Bg[g][brr][bk + 3] = w4.w;
            }
        }
        __syncthreads();
#pragma unroll
        for (int kk = 0; kk < 32; kk += 2) {
            float2 u0 = *(const float2*)&Au[tr][kk];
            float2 u1 = *(const float2*)&Au[tr + 8][kk];
            float2 h0 = *(const float2*)&Ah[tr][kk];
            float2 h1v = *(const float2*)&Ah[tr + 8][kk];
#pragma unroll
            for (int g = 0; g < 6; g++) {
                float2 b2 = *(const float2*)&Bg[g][tc][kk];
                if (g < 3) {
                    acc[g][0] += u0.x * b2.x + u0.y * b2.y;
                    acc[g][1] += u1.x * b2.x + u1.y * b2.y;
                } else {
                    acc[g][0] += h0.x * b2.x + h0.y * b2.y;
                    acc[g][1] += h1v.x * b2.x + h1v.y * b2.y;
                }
            }
        }
    }
    int col = bn + tc;
#pragma unroll
    for (int r = 0; r < 2; r++) {
        int row = bm + tr + r * 8;
        float ir = acc[0][r] + bih[col];
        float iz = acc[1][r] + bih[col + 256];
        float in_ = acc[2][r] + bih[col + 512];
        float hr = acc[3][r] + bhh[col];
        float hz = acc[4][r] + bhh[col + 256];
        float hn = acc[5][r] + bhh[col + 512];
        float rg = sigmoidf_(ir + hr);
        float z = sigmoidf_(iz + hz);
        float nn = tanhf(in_ + rg * hn);
        float h = slots[(size_t)row * 256 + col];
        out[(size_t)row * 256 + col] = (1.0f - z) * nn + z * h;
    }
}

extern "C" void kernel_launch(void* const* d_in, const int* in_sizes, int n_in,
                              void* d_out, int out_size) {
    const float* inputs    = (const float*)d_in[0];
    const float* noise     = (const float*)d_in[1];
    const float* slots_mu  = (const float*)d_in[2];
    const float* slots_ls  = (const float*)d_in[3];
    const float* Wq        = (const float*)d_in[4];
    const float* Wk        = (const float*)d_in[5];
    const float* Wv        = (const float*)d_in[6];
    const float* gru_wih   = (const float*)d_in[7];
    const float* gru_whh   = (const float*)d_in[8];
    const float* gru_bih   = (const float*)d_in[9];
    const float* gru_bhh   = (const float*)d_in[10];
    const float* mlp_w1    = (const float*)d_in[11];
    const float* mlp_b1    = (const float*)d_in[12];
    const float* mlp_w2    = (const float*)d_in[13];
    const float* mlp_b2    = (const float*)d_in[14];
    const float* ln_in_g   = (const float*)d_in[15];
    const float* ln_in_b   = (const float*)d_in[16];
    const float* ln_s_g    = (const float*)d_in[17];
    const float* ln_s_b    = (const float*)d_in[18];
    const float* ln_ff_g   = (const float*)d_in[19];
    const float* ln_ff_b   = (const float*)d_in[20];

    float* S = nullptr;
    cudaGetSymbolAddress((void**)&S, g_scratch);
    __nv_bfloat16* wb = nullptr;
    cudaGetSymbolAddress((void**)&wb, g_wb);
    float* kv    = S + OFF_KV;
    float* slots = S + OFF_SLOTS;
    float* gbuf  = S + OFF_GBUF;
    float* qbuf  = S + OFF_Q;
    float* h1    = S + OFF_H1;
    float* updp  = S + OFF_UPDP;
    float* rsp   = S + OFF_RSP;
    float* S1kv  = S + OFF_S1KV;
    float* S2kv  = S + OFF_S2KV;
    float* Wqp   = S + OFF_WQP;
    float* S1q   = S + OFF_S1Q;
    float* S2q   = S + OFF_S2Q;
    float* W1p   = S + OFF_W1P;
    float* S1m   = S + OFF_S1M;
    float* S2m   = S + OFF_S2M;

    // 0: all preps + slot init
    setup_kernel<<<480, 256>>>(Wk, Wv, ln_in_g, ln_in_b, wb, S1kv, S2kv,
                               Wq, ln_s_g, ln_s_b, Wqp, S1q, S2q,
                               mlp_w1, ln_ff_g, ln_ff_b, W1p, S1m, S2m,
                               slots_mu, slots_ls, noise, slots);
    // 1: KV projection
    kv_mma_kernel<<<dim3(4, 256), 256>>>(inputs, wb, S1kv, S2kv, kv);

    for (int it = 0; it < ITERS; it++) {
        // q = LN(slots)@W'q * SCALE   (launch 2 on it0)
        gemm16_kernel<32, true, false, false, true><<<dim3(8, 16), 256>>>(
            slots, Wqp, S1q, S2q, nullptr, nullptr, qbuf, 256, 256);
        // attn partials                (launch 3 on it0 -> profiled)
        attn2_kernel<<<dim3(32, NCHUNK), 256>>>(qbuf, kv, updp, rsp);
        // GRU (updp reduce inline)
        gru16_kernel<<<dim3(8, 16), 256>>>(updp, rsp, slots,
            gru_wih, gru_whh, gru_bih, gru_bhh, gbuf);
        // mlp1 = relu(LN(gbuf)@W'1 + b1)
        gemm16_kernel<128, true, true, false, false><<<dim3(8, 16), 256>>>(
            gbuf, W1p, S1m, S2m, mlp_b1, nullptr, h1, 1024, 256);
        // mlp2 = h1@W2 + b2 + gbuf
        float* outp = (it == ITERS - 1) ? (float*)d_out : slots;
        gemm16_kernel<32, false, false, true, false><<<dim3(8, 16), 256>>>(
            h1, mlp_w2, nullptr, nullptr, mlp_b2, gbuf, outp, 256, 1024);
    }
}

// round 12
// speedup vs baseline: 1.8351x; 1.1997x over previous
#include <cuda_runtime.h>
#include <cuda_bf16.h>
#include <math.h>
#include <cstdint>

// ---------------------------------------------------------------------------
// SlotAttention: b=32, n=1024, c=256, d=256, S=8 slots, 3 iters.
// KV: bf16 m16n8k16 mma.sync (tcgen05 rejected by compute_103 PTX stage).
// attn: 512 blocks (64-j chunks), prefetched dots, batched updates.
// ---------------------------------------------------------------------------
#define NTOK 1024
#define ITERS 3
#define TOKROWS 32768
#define SROWS 256
#define SCALE_F 0.0625f
#define EPS_F 1e-8f
#define NCHUNK 16               // attn j-chunks of 64

// scratch arena (floats)
#define OFF_KV     0                                  // 32768*512
#define OFF_SLOTS  (OFF_KV + TOKROWS*512)             // 256*256
#define OFF_GBUF   (OFF_SLOTS + SROWS*256)
#define OFF_Q      (OFF_GBUF + SROWS*256)
#define OFF_H1     (OFF_Q + SROWS*256)                // 256*1024
#define OFF_UPDP   (OFF_H1 + SROWS*1024)              // 16*256*256
#define OFF_RSP    (OFF_UPDP + NCHUNK*SROWS*256)      // 16*256
#define OFF_S1KV   (OFF_RSP + NCHUNK*SROWS)           // 512
#define OFF_S2KV   (OFF_S1KV + 512)
#define OFF_WQP    (OFF_S2KV + 512)                   // 256*256 row-major
#define OFF_S1Q    (OFF_WQP + 256*256)
#define OFF_S2Q    (OFF_S1Q + 256)
#define OFF_W1P    (OFF_S2Q + 256)                    // 1024*256
#define OFF_S1M    (OFF_W1P + 1024*256)
#define OFF_S2M    (OFF_S1M + 1024)
#define SCRATCH_FLOATS (OFF_S2M + 1024)

__device__ float g_scratch[SCRATCH_FLOATS];
__device__ __align__(16) __nv_bfloat16 g_wb[512 * 256];

__device__ __forceinline__ float warp_sum(float v) {
#pragma unroll
    for (int o = 16; o > 0; o >>= 1) v += __shfl_xor_sync(0xffffffffu, v, o);
    return v;
}
__device__ __forceinline__ float grp8_sum(float v) {
    v += __shfl_xor_sync(0xffffffffu, v, 4);
    v += __shfl_xor_sync(0xffffffffu, v, 2);
    v += __shfl_xor_sync(0xffffffffu, v, 1);
    return v;
}
__device__ __forceinline__ float sigmoidf_(float x) { return 1.0f / (1.0f + __expf(-x)); }

__device__ __forceinline__ void mma16(float* d, const unsigned* a, const unsigned* b) {
    asm volatile("mma.sync.aligned.m16n8k16.row.col.f32.bf16.bf16.f32 "
        "{%0,%1,%2,%3}, {%4,%5,%6,%7}, {%8,%9}, {%0,%1,%2,%3};"
        : "+f"(d[0]), "+f"(d[1]), "+f"(d[2]), "+f"(d[3])
        : "r"(a[0]), "r"(a[1]), "r"(a[2]), "r"(a[3]), "r"(b[0]), "r"(b[1]));
}

// ---------------------------------------------------------------------------
// setup: all weight preps + slot init in ONE kernel (grid 480).
// ---------------------------------------------------------------------------
__global__ void setup_kernel(
    const float* __restrict__ Wk, const float* __restrict__ Wv,
    const float* __restrict__ ln_in_g, const float* __restrict__ ln_in_b,
    __nv_bfloat16* __restrict__ wb, float* __restrict__ S1kv, float* __restrict__ S2kv,
    const float* __restrict__ Wq, const float* __restrict__ ln_s_g, const float* __restrict__ ln_s_b,
    float* __restrict__ Wqp, float* __restrict__ S1q, float* __restrict__ S2q,
    const float* __restrict__ W1, const float* __restrict__ ln_ff_g, const float* __restrict__ ln_ff_b,
    float* __restrict__ W1p, float* __restrict__ S1m, float* __restrict__ S2m,
    const float* __restrict__ mu, const float* __restrict__ ls,
    const float* __restrict__ noise, float* __restrict__ slots) {
    int blk = blockIdx.x;
    int w = threadIdx.x >> 5, lane = threadIdx.x & 31;
    if (blk < 64) {
        int n = blk * 8 + w;
        const float* src = (n < 256) ? Wk + (size_t)n * 256 : Wv + (size_t)(n - 256) * 256;
        float s1 = 0.f, s2 = 0.f;
#pragma unroll
        for (int u = 0; u < 8; u++) {
            int c = u * 32 + lane;
            __nv_bfloat16 bf = __float2bfloat16(src[c] * ln_in_g[c]);
            wb[(size_t)n * 256 + c] = bf;
            s1 += __bfloat162float(bf);
            s2 += src[c] * ln_in_b[c];
        }
        s1 = warp_sum(s1); s2 = warp_sum(s2);
        if (lane == 0) { S1kv[n] = s1; S2kv[n] = s2; }
    } else if (blk < 96) {
        int n = (blk - 64) * 8 + w;
        float s1 = 0.f, s2 = 0.f;
#pragma unroll
        for (int u = 0; u < 8; u++) {
            int c = u * 32 + lane;
            float wv = Wq[(size_t)n * 256 + c] * ln_s_g[c];
            Wqp[(size_t)n * 256 + c] = wv;
            s1 += wv;
            s2 += Wq[(size_t)n * 256 + c] * ln_s_b[c];
        }
        s1 = warp_sum(s1); s2 = warp_sum(s2);
        if (lane == 0) { S1q[n] = s1; S2q[n] = s2; }
    } else if (blk < 224) {
        int n = (blk - 96) * 8 + w;
        float s1 = 0.f, s2 = 0.f;
#pragma unroll
        for (int u = 0; u < 8; u++) {
            int c = u * 32 + lane;
            float wv = W1[(size_t)n * 256 + c] * ln_ff_g[c];
            W1p[(size_t)n * 256 + c] = wv;
            s1 += wv;
            s2 += W1[(size_t)n * 256 + c] * ln_ff_b[c];
        }
        s1 = warp_sum(s1); s2 = warp_sum(s2);
        if (lane == 0) { S1m[n] = s1; S2m[n] = s2; }
    } else {
        int idx = (blk - 224) * 256 + threadIdx.x;
        int d = idx & 255;
        slots[idx] = mu[d] + __expf(ls[d]) * noise[idx];
    }
}

// ---------------------------------------------------------------------------
// KV GEMM (unchanged, 74.7us measured): bf16 m16n8k16, LN-fold.
// ---------------------------------------------------------------------------
__global__ __launch_bounds__(256) void kv_mma_kernel(
    const float* __restrict__ x, const __nv_bfloat16* __restrict__ wb,
    const float* __restrict__ S1, const float* __restrict__ S2,
    float* __restrict__ C) {
    __shared__ uint32_t As[128][20];
    __shared__ uint32_t Bs[128][20];
    __shared__ float rowm[128], rowr[128];
    int t = threadIdx.x;
    int bm = blockIdx.y * 128, bn = blockIdx.x * 128;
    int w = t >> 5, lane = t & 31;
    int m0 = (w >> 2) * 64, n0 = (w & 3) * 32;
    int g = lane >> 2, tig = lane & 3;
    float acc[4][4][4];
#pragma unroll
    for (int a = 0; a < 4; a++)
#pragma unroll
        for (int bq = 0; bq < 4; bq++)
#pragma unroll
            for (int c = 0; c < 4; c++) acc[a][bq][c] = 0.f;

    int lm = t >> 3;
    int lkf = (t & 7) * 4;
    int lku = (t & 7) * 2;

    float4 ar[4]; uint2 br[4];
    float sA[4] = {0.f, 0.f, 0.f, 0.f}, s2A[4] = {0.f, 0.f, 0.f, 0.f};
#pragma unroll
    for (int r = 0; r < 4; r++) {
        ar[r] = *(const float4*)(x + (size_t)(bm + r * 32 + lm) * 256 + lkf);
        br[r] = *(const uint2*)(wb + (size_t)(bn + r * 32 + lm) * 256 + lkf);
    }
    for (int it = 0; it < 8; it++) {
#pragma unroll
        for (int r = 0; r < 4; r++) {
            sA[r] += ar[r].x + ar[r].y + ar[r].z + ar[r].w;
            s2A[r] += ar[r].x * ar[r].x + ar[r].y * ar[r].y + ar[r].z * ar[r].z + ar[r].w * ar[r].w;
        }
        __syncthreads();
#pragma unroll
        for (int r = 0; r < 4; r++) {
            int m = r * 32 + lm;
            __nv_bfloat162 p0 = __floats2bfloat162_rn(ar[r].x, ar[r].y);
            __nv_bfloat162 p1 = __floats2bfloat162_rn(ar[r].z, ar[r].w);
            As[m][lku + 0] = *(uint32_t*)&p0;
            As[m][lku + 1] = *(uint32_t*)&p1;
            Bs[m][lku + 0] = br[r].x;
            Bs[m][lku + 1] = br[r].y;
        }
        __syncthreads();
        if (it < 7) {
            int c = (it + 1) * 32 + lkf;
#pragma unroll
            for (int r = 0; r < 4; r++) {
                ar[r] = *(const float4*)(x + (size_t)(bm + r * 32 + lm) * 256 + c);
                br[r] = *(const uint2*)(wb + (size_t)(bn + r * 32 + lm) * 256 + c);
            }
        }
#pragma unroll
        for (int ks = 0; ks < 2; ks++) {
            unsigned a[4][4], b[4][2];
#pragma unroll
            for (int mt = 0; mt < 4; mt++) {
                int mr = m0 + mt * 16 + g;
                a[mt][0] = As[mr][ks * 8 + tig];
                a[mt][1] = As[mr + 8][ks * 8 + tig];
                a[mt][2] = As[mr][ks * 8 + tig + 4];
                a[mt][3] = As[mr + 8][ks * 8 + tig + 4];
            }
#pragma unroll
            for (int nt = 0; nt < 4; nt++) {
                int nr = n0 + nt * 8 + g;
                b[nt][0] = Bs[nr][ks * 8 + tig];
                b[nt][1] = Bs[nr][ks * 8 + tig + 4];
            }
#pragma unroll
            for (int mt = 0; mt < 4; mt++)
#pragma unroll
                for (int nt = 0; nt < 4; nt++)
                    mma16(acc[mt][nt], a[mt], b[nt]);
        }
    }
#pragma unroll
    for (int r = 0; r < 4; r++) {
        float s = grp8_sum(sA[r]);
        float s2 = grp8_sum(s2A[r]);
        if ((t & 7) == 0) {
            float m = s * (1.0f / 256.0f);
            float var = s2 * (1.0f / 256.0f) - m * m;
            rowm[r * 32 + lm] = m;
            rowr[r * 32 + lm] = rsqrtf(var + 1e-5f);
        }
    }
    __syncthreads();
#pragma unroll
    for (int mt = 0; mt < 4; mt++)
#pragma unroll
        for (int nt = 0; nt < 4; nt++) {
            int lr = m0 + mt * 16 + g;
            int col = bn + n0 + nt * 8 + tig * 2;
            float s1a = S1[col], s1b = S1[col + 1], s2a = S2[col], s2b = S2[col + 1];
            float m0v = rowm[lr], r0v = rowr[lr];
            float m1v = rowm[lr + 8], r1v = rowr[lr + 8];
            float2 o0 = make_float2(r0v * acc[mt][nt][0] - r0v * m0v * s1a + s2a,
                                    r0v * acc[mt][nt][1] - r0v * m0v * s1b + s2b);
            float2 o1 = make_float2(r1v * acc[mt][nt][2] - r1v * m1v * s1a + s2a,
                                    r1v * acc[mt][nt][3] - r1v * m1v * s1b + s2b);
            *(float2*)(C + (size_t)(bm + lr) * 512 + col) = o0;
            *(float2*)(C + (size_t)(bm + lr + 8) * 512 + col) = o1;
        }
}

// ---------------------------------------------------------------------------
// gemm16: 16-row x NC-col tiles, 256 threads, register-prefetched BK=32.
// ---------------------------------------------------------------------------
template<int NC, bool LNF, bool RELU, bool ADDOUT, bool QSC>
__global__ __launch_bounds__(256) void gemm16_kernel(
    const float* __restrict__ A, const float* __restrict__ B,
    const float* __restrict__ S1, const float* __restrict__ S2,
    const float* __restrict__ bias, const float* __restrict__ addsrc,
    float* __restrict__ C, int N, int K) {
    constexpr int CPT = NC / 32;
    __shared__ float As[16][34];
    __shared__ float Bs[NC][34];
    __shared__ float rowm[16], rowr[16];
    int t = threadIdx.x;
    int bm = blockIdx.y * 16, bn = blockIdx.x * NC;
    if (LNF) {
        int w = t >> 5, lane = t & 31;
#pragma unroll
        for (int rr = 0; rr < 2; rr++) {
            int row = w * 2 + rr;
            const float* p = A + (size_t)(bm + row) * 256;
            float s = 0.f, s2 = 0.f;
#pragma unroll
            for (int u = 0; u < 8; u++) { float v = p[lane + u * 32]; s += v; s2 += v * v; }
            s = warp_sum(s); s2 = warp_sum(s2);
            if (lane == 0) {
                float m = s * (1.0f / 256.0f);
                float var = s2 * (1.0f / 256.0f) - m * m;
                rowm[row] = m; rowr[row] = rsqrtf(var + 1e-5f);
            }
        }
    }
    int ar = t >> 4, ak = (t & 15) * 2;
    int brr = t >> 3, bk = (t & 7) * 4;
    int tr = t >> 5, tc = t & 31;
    float acc[2][CPT];
#pragma unroll
    for (int r = 0; r < 2; r++)
#pragma unroll
        for (int c = 0; c < CPT; c++) acc[r][c] = 0.f;

    float2 pa = *(const float2*)(A + (size_t)(bm + ar) * K + ak);
    float4 pb[CPT];
#pragma unroll
    for (int c = 0; c < CPT; c++)
        pb[c] = *(const float4*)(B + (size_t)(bn + c * 32 + brr) * K + bk);

    int KT = K >> 5;
    for (int kt = 0; kt < KT; kt++) {
        __syncthreads();
        As[ar][ak] = pa.x; As[ar][ak + 1] = pa.y;
#pragma unroll
        for (int c = 0; c < CPT; c++) {
            Bs[c * 32 + brr][bk + 0] = pb[c].x; Bs[c * 32 + brr][bk + 1] = pb[c].y;
            Bs[c * 32 + brr][bk + 2] = pb[c].z; Bs[c * 32 + brr][bk + 3] = pb[c].w;
        }
        __syncthreads();
        if (kt + 1 < KT) {
            int k0 = (kt + 1) * 32;
            pa = *(const float2*)(A + (size_t)(bm + ar) * K + k0 + ak);
#pragma unroll
            for (int c = 0; c < CPT; c++)
                pb[c] = *(const float4*)(B + (size_t)(bn + c * 32 + brr) * K + k0 + bk);
        }
#pragma unroll
        for (int kk = 0; kk < 32; kk += 2) {
            float2 a0 = *(const float2*)&As[tr][kk];
            float2 a1 = *(const float2*)&As[tr + 8][kk];
#pragma unroll
            for (int c = 0; c < CPT; c++) {
                float2 b2 = *(const float2*)&Bs[tc + c * 32][kk];
                acc[0][c] += a0.x * b2.x + a0.y * b2.y;
                acc[1][c] += a1.x * b2.x + a1.y * b2.y;
            }
        }
    }
#pragma unroll
    for (int r = 0; r < 2; r++) {
        int lr = tr + r * 8;
        int row = bm + lr;
#pragma unroll
        for (int c = 0; c < CPT; c++) {
            int col = bn + c * 32 + tc;
            float v = acc[r][c];
            if (LNF) { float m = rowm[lr], rs = rowr[lr]; v = rs * v - rs * m * S1[col] + S2[col]; }
            if (bias) v += bias[col];
            if (RELU) v = fmaxf(v, 0.f);
            if (QSC) v *= SCALE_F;
            if (ADDOUT) v += addsrc[(size_t)row * N + col];
            C[(size_t)row * N + col] = v;
        }
    }
}

// ---------------------------------------------------------------------------
// attention: dots + softmax over slots + updates partials.
// grid (32 batches, 16 j-chunks of 64). Prefetched k rows, batched v loads.
// ---------------------------------------------------------------------------
__global__ __launch_bounds__(256) void attn2_kernel(
    const float* __restrict__ qbuf, const float* __restrict__ kv,
    float* __restrict__ updp, float* __restrict__ rsp) {
    __shared__ float qs[8][256];
    __shared__ float attn_s[64][9];
    __shared__ float rswarp[8][8];
    int b = blockIdx.x, jc = blockIdx.y;
    int t = threadIdx.x, w = t >> 5, lane = t & 31;

#pragma unroll
    for (int u = 0; u < 8; u++)
        qs[u][t] = qbuf[(size_t)(b * 8 + u) * 256 + t];
    __syncthreads();

    // dots + softmax: warp w handles jl = w + 8*jj, jj in [0,8). Prefetch next k row.
    float rsa = 0.f;
    {
        const float* kbase = kv + ((size_t)b * NTOK + jc * 64) * 512;
        float kr0[8], kr1[8];
#pragma unroll
        for (int u = 0; u < 8; u++) kr0[u] = kbase[(size_t)w * 512 + u * 32 + lane];
#pragma unroll 1
        for (int jj = 0; jj < 8; jj++) {
            int jl = w + jj * 8;
            if (jj < 7) {
#pragma unroll
                for (int u = 0; u < 8; u++)
                    kr1[u] = kbase[(size_t)(jl + 8) * 512 + u * 32 + lane];
            }
            float dv[8];
#pragma unroll
            for (int i = 0; i < 8; i++) {
                float p = 0.f;
#pragma unroll
                for (int u = 0; u < 8; u++) p += qs[i][u * 32 + lane] * kr0[u];
                dv[i] = warp_sum(p);
            }
            float mx = dv[0];
#pragma unroll
            for (int i = 1; i < 8; i++) mx = fmaxf(mx, dv[i]);
            float se = 0.f, ev[8];
#pragma unroll
            for (int i = 0; i < 8; i++) { ev[i] = __expf(dv[i] - mx); se += ev[i]; }
            float inv = 1.0f / se;
            float my = 0.f;
#pragma unroll
            for (int i = 0; i < 8; i++) {
                float a = ev[i] * inv + EPS_F;
                if (lane == i) my = a;
            }
            if (lane < 8) { attn_s[jl][lane] = my; rsa += my; }
#pragma unroll
            for (int u = 0; u < 8; u++) kr0[u] = kr1[u];
        }
    }
    if (lane < 8) rswarp[w][lane] = rsa;
    __syncthreads();

    // updates: thread t = value col; 8-wide batched v loads.
    {
        float uacc[8];
#pragma unroll
        for (int i = 0; i < 8; i++) uacc[i] = 0.f;
        const float* vbase = kv + ((size_t)b * NTOK + jc * 64) * 512 + 256 + t;
#pragma unroll 1
        for (int j0 = 0; j0 < 64; j0 += 8) {
            float va[8];
#pragma unroll
            for (int r = 0; r < 8; r++) va[r] = vbase[(size_t)(j0 + r) * 512];
#pragma unroll
            for (int r = 0; r < 8; r++)
#pragma unroll
                for (int i = 0; i < 8; i++) uacc[i] += attn_s[j0 + r][i] * va[r];
        }
#pragma unroll
        for (int i = 0; i < 8; i++)
            updp[((size_t)jc * SROWS + b * 8 + i) * 256 + t] = uacc[i];
        if (t < 8) {
            float r = 0.f;
#pragma unroll
            for (int ww = 0; ww < 8; ww++) r += rswarp[ww][t];
            rsp[jc * SROWS + b * 8 + t] = r;
        }
    }
}

// ---------------------------------------------------------------------------
// GRU, 16x32 units, updp reduction inline. grid (8, 16) = 128 blocks.
// ---------------------------------------------------------------------------
__global__ __launch_bounds__(256) void gru16_kernel(
    const float* __restrict__ updp, const float* __restrict__ rsp,
    const float* __restrict__ slots,
    const float* __restrict__ wih, const float* __restrict__ whh,
    const float* __restrict__ bih, const float* __restrict__ bhh,
    float* __restrict__ out) {
    __shared__ float Au[16][34], Ah[16][34];
    __shared__ float Bg[6][32][34];
    __shared__ float invrs[16];
    int t = threadIdx.x;
    int bm = blockIdx.y * 16, bn = blockIdx.x * 32;
    if (t < 16) {
        float rs = 0.f;
#pragma unroll
        for (int p = 0; p < NCHUNK; p++) rs += rsp[p * 256 + bm + t];
        invrs[t] = 1.0f / rs;
    }
    int ar = t >> 4, ak = (t & 15) * 2;
    int brr = t >> 3, bk = (t & 7) * 4;
    int tr = t >> 5, tc = t & 31;
    float acc[6][2];
#pragma unroll
    for (int g = 0; g < 6; g++) { acc[g][0] = 0.f; acc[g][1] = 0.f; }

    for (int kt = 0; kt < 8; kt++) {
        int k0 = kt * 32;
        __syncthreads();
        {
            size_t base = (size_t)(bm + ar) * 256 + k0 + ak;
            float sx = 0.f, sy = 0.f;
#pragma unroll
            for (int p = 0; p < NCHUNK; p++) {
                float2 v = *(const float2*)(updp + (size_t)p * 65536 + base);
                sx += v.x; sy += v.y;
            }
            float iv = invrs[ar];
            Au[ar][ak] = sx * iv; Au[ar][ak + 1] = sy * iv;
            float2 h2 = *(const float2*)(slots + base);
            Ah[ar][ak] = h2.x; Ah[ar][ak + 1] = h2.y;
#pragma unroll
            for (int g = 0; g < 6; g++) {
                const float* W = (g < 3) ? wih : whh;
                float4 w4 = *(const float4*)(W + (size_t)((g % 3) * 256 + bn + brr) * 256 + k0 + bk);
                Bg[g][brr][bk + 0] = w4.x; Bg[g][brr][bk + 1] = w4.y;
                Bg[g][brr][bk + 2] = w4.z; Bg[g][brr][bk + 3] = w4.w;
            }
        }
        __syncthreads();
#pragma unroll
        for (int kk = 0; kk < 32; kk += 2) {
            float2 u0 = *(const float2*)&Au[tr][kk];
            float2 u1 = *(const float2*)&Au[tr + 8][kk];
            float2 h0 = *(const float2*)&Ah[tr][kk];
            float2 h1v = *(const float2*)&Ah[tr + 8][kk];
#pragma unroll
            for (int g = 0; g < 6; g++) {
                float2 b2 = *(const float2*)&Bg[g][tc][kk];
                if (g < 3) {
                    acc[g][0] += u0.x * b2.x + u0.y * b2.y;
                    acc[g][1] += u1.x * b2.x + u1.y * b2.y;
                } else {
                    acc[g][0] += h0.x * b2.x + h0.y * b2.y;
                    acc[g][1] += h1v.x * b2.x + h1v.y * b2.y;
                }
            }
        }
    }
    int col = bn + tc;
#pragma unroll
    for (int r = 0; r < 2; r++) {
        int row = bm + tr + r * 8;
        float ir = acc[0][r] + bih[col];
        float iz = acc[1][r] + bih[col + 256];
        float in_ = acc[2][r] + bih[col + 512];
        float hr = acc[3][r] + bhh[col];
        float hz = acc[4][r] + bhh[col + 256];
        float hn = acc[5][r] + bhh[col + 512];
        float rg = sigmoidf_(ir + hr);
        float z = sigmoidf_(iz + hz);
        float nn = tanhf(in_ + rg * hn);
        float h = slots[(size_t)row * 256 + col];
        out[(size_t)row * 256 + col] = (1.0f - z) * nn + z * h;
    }
}

extern "C" void kernel_launch(void* const* d_in, const int* in_sizes, int n_in,
                              void* d_out, int out_size) {
    const float* inputs    = (const float*)d_in[0];
    const float* noise     = (const float*)d_in[1];
    const float* slots_mu  = (const float*)d_in[2];
    const float* slots_ls  = (const float*)d_in[3];
    const float* Wq        = (const float*)d_in[4];
    const float* Wk        = (const float*)d_in[5];
    const float* Wv        = (const float*)d_in[6];
    const float* gru_wih   = (const float*)d_in[7];
    const float* gru_whh   = (const float*)d_in[8];
    const float* gru_bih   = (const float*)d_in[9];
    const float* gru_bhh   = (const float*)d_in[10];
    const float* mlp_w1    = (const float*)d_in[11];
    const float* mlp_b1    = (const float*)d_in[12];
    const float* mlp_w2    = (const float*)d_in[13];
    const float* mlp_b2    = (const float*)d_in[14];
    const float* ln_in_g   = (const float*)d_in[15];
    const float* ln_in_b   = (const float*)d_in[16];
    const float* ln_s_g    = (const float*)d_in[17];
    const float* ln_s_b    = (const float*)d_in[18];
    const float* ln_ff_g   = (const float*)d_in[19];
    const float* ln_ff_b   = (const float*)d_in[20];

    float* S = nullptr;
    cudaGetSymbolAddress((void**)&S, g_scratch);
    __nv_bfloat16* wb = nullptr;
    cudaGetSymbolAddress((void**)&wb, g_wb);
    float* kv    = S + OFF_KV;
    float* slots = S + OFF_SLOTS;
    float* gbuf  = S + OFF_GBUF;
    float* qbuf  = S + OFF_Q;
    float* h1    = S + OFF_H1;
    float* updp  = S + OFF_UPDP;
    float* rsp   = S + OFF_RSP;
    float* S1kv  = S + OFF_S1KV;
    float* S2kv  = S + OFF_S2KV;
    float* Wqp   = S + OFF_WQP;
    float* S1q   = S + OFF_S1Q;
    float* S2q   = S + OFF_S2Q;
    float* W1p   = S + OFF_W1P;
    float* S1m   = S + OFF_S1M;
    float* S2m   = S + OFF_S2M;

    // 0: all preps + slot init
    setup_kernel<<<480, 256>>>(Wk, Wv, ln_in_g, ln_in_b, wb, S1kv, S2kv,
                               Wq, ln_s_g, ln_s_b, Wqp, S1q, S2q,
                               mlp_w1, ln_ff_g, ln_ff_b, W1p, S1m, S2m,
                               slots_mu, slots_ls, noise, slots);
    // 1: KV projection
    kv_mma_kernel<<<dim3(4, 256), 256>>>(inputs, wb, S1kv, S2kv, kv);

    for (int it = 0; it < ITERS; it++) {
        // q = LN(slots)@W'q * SCALE   (launch 2 on it0)
        gemm16_kernel<32, true, false, false, true><<<dim3(8, 16), 256>>>(
            slots, Wqp, S1q, S2q, nullptr, nullptr, qbuf, 256, 256);
        // attn partials                (launch 3 on it0 -> profiled)
        attn2_kernel<<<dim3(32, NCHUNK), 256>>>(qbuf, kv, updp, rsp);
        // GRU (updp reduce inline)
        gru16_kernel<<<dim3(8, 16), 256>>>(updp, rsp, slots,
            gru_wih, gru_whh, gru_bih, gru_bhh, gbuf);
        // mlp1 = relu(LN(gbuf)@W'1 + b1)
        gemm16_kernel<64, true, true, false, false><<<dim3(16, 16), 256>>>(
            gbuf, W1p, S1m, S2m, mlp_b1, nullptr, h1, 1024, 256);
        // mlp2 = h1@W2 + b2 + gbuf
        float* outp = (it == ITERS - 1) ? (float*)d_out : slots;
        gemm16_kernel<32, false, false, true, false><<<dim3(8, 16), 256>>>(
            h1, mlp_w2, nullptr, nullptr, mlp_b2, gbuf, outp, 256, 1024);
    }
}

// round 13
// speedup vs baseline: 1.9313x; 1.0524x over previous
#include <cuda_runtime.h>
#include <cuda_bf16.h>
#include <math.h>
#include <cstdint>

// ---------------------------------------------------------------------------
// SlotAttention: b=32, n=1024, c=256, d=256, S=8 slots, 3 iters.
// KV: bf16 m16n8k16 mma.sync, bf16 kv storage (halves attn traffic).
// kv_mma: BN=64, 2 CTAs/SM. attn: 512 blocks, bf16 loads.
// ---------------------------------------------------------------------------
#define NTOK 1024
#define ITERS 3
#define TOKROWS 32768
#define SROWS 256
#define SCALE_F 0.0625f
#define EPS_F 1e-8f
#define NCHUNK 16               // attn j-chunks of 64

// scratch arena (floats)
#define OFF_KV     0                                  // bf16[32768*512] lives here
#define OFF_SLOTS  (OFF_KV + TOKROWS*256)             // (kv uses half the float space)
#define OFF_GBUF   (OFF_SLOTS + SROWS*256)
#define OFF_Q      (OFF_GBUF + SROWS*256)
#define OFF_H1     (OFF_Q + SROWS*256)                // 256*1024
#define OFF_UPDP   (OFF_H1 + SROWS*1024)              // 16*256*256
#define OFF_RSP    (OFF_UPDP + NCHUNK*SROWS*256)      // 16*256
#define OFF_S1KV   (OFF_RSP + NCHUNK*SROWS)           // 512
#define OFF_S2KV   (OFF_S1KV + 512)
#define OFF_WQP    (OFF_S2KV + 512)                   // 256*256 row-major
#define OFF_S1Q    (OFF_WQP + 256*256)
#define OFF_S2Q    (OFF_S1Q + 256)
#define OFF_W1P    (OFF_S2Q + 256)                    // 1024*256
#define OFF_S1M    (OFF_W1P + 1024*256)
#define OFF_S2M    (OFF_S1M + 1024)
#define SCRATCH_FLOATS (OFF_S2M + 1024)

__device__ __align__(16) float g_scratch[SCRATCH_FLOATS];
__device__ __align__(16) __nv_bfloat16 g_wb[512 * 256];

__device__ __forceinline__ float warp_sum(float v) {
#pragma unroll
    for (int o = 16; o > 0; o >>= 1) v += __shfl_xor_sync(0xffffffffu, v, o);
    return v;
}
__device__ __forceinline__ float grp8_sum(float v) {
    v += __shfl_xor_sync(0xffffffffu, v, 4);
    v += __shfl_xor_sync(0xffffffffu, v, 2);
    v += __shfl_xor_sync(0xffffffffu, v, 1);
    return v;
}
__device__ __forceinline__ float sigmoidf_(float x) { return 1.0f / (1.0f + __expf(-x)); }

__device__ __forceinline__ void mma16(float* d, const unsigned* a, const unsigned* b) {
    asm volatile("mma.sync.aligned.m16n8k16.row.col.f32.bf16.bf16.f32 "
        "{%0,%1,%2,%3}, {%4,%5,%6,%7}, {%8,%9}, {%0,%1,%2,%3};"
        : "+f"(d[0]), "+f"(d[1]), "+f"(d[2]), "+f"(d[3])
        : "r"(a[0]), "r"(a[1]), "r"(a[2]), "r"(a[3]), "r"(b[0]), "r"(b[1]));
}

// ---------------------------------------------------------------------------
// setup: all weight preps + slot init in ONE kernel (grid 480).
// ---------------------------------------------------------------------------
__global__ void setup_kernel(
    const float* __restrict__ Wk, const float* __restrict__ Wv,
    const float* __restrict__ ln_in_g, const float* __restrict__ ln_in_b,
    __nv_bfloat16* __restrict__ wb, float* __restrict__ S1kv, float* __restrict__ S2kv,
    const float* __restrict__ Wq, const float* __restrict__ ln_s_g, const float* __restrict__ ln_s_b,
    float* __restrict__ Wqp, float* __restrict__ S1q, float* __restrict__ S2q,
    const float* __restrict__ W1, const float* __restrict__ ln_ff_g, const float* __restrict__ ln_ff_b,
    float* __restrict__ W1p, float* __restrict__ S1m, float* __restrict__ S2m,
    const float* __restrict__ mu, const float* __restrict__ ls,
    const float* __restrict__ noise, float* __restrict__ slots) {
    int blk = blockIdx.x;
    int w = threadIdx.x >> 5, lane = threadIdx.x & 31;
    if (blk < 64) {
        int n = blk * 8 + w;
        const float* src = (n < 256) ? Wk + (size_t)n * 256 : Wv + (size_t)(n - 256) * 256;
        float s1 = 0.f, s2 = 0.f;
#pragma unroll
        for (int u = 0; u < 8; u++) {
            int c = u * 32 + lane;
            __nv_bfloat16 bf = __float2bfloat16(src[c] * ln_in_g[c]);
            wb[(size_t)n * 256 + c] = bf;
            s1 += __bfloat162float(bf);
            s2 += src[c] * ln_in_b[c];
        }
        s1 = warp_sum(s1); s2 = warp_sum(s2);
        if (lane == 0) { S1kv[n] = s1; S2kv[n] = s2; }
    } else if (blk < 96) {
        int n = (blk - 64) * 8 + w;
        float s1 = 0.f, s2 = 0.f;
#pragma unroll
        for (int u = 0; u < 8; u++) {
            int c = u * 32 + lane;
            float wv = Wq[(size_t)n * 256 + c] * ln_s_g[c];
            Wqp[(size_t)n * 256 + c] = wv;
            s1 += wv;
            s2 += Wq[(size_t)n * 256 + c] * ln_s_b[c];
        }
        s1 = warp_sum(s1); s2 = warp_sum(s2);
        if (lane == 0) { S1q[n] = s1; S2q[n] = s2; }
    } else if (blk < 224) {
        int n = (blk - 96) * 8 + w;
        float s1 = 0.f, s2 = 0.f;
#pragma unroll
        for (int u = 0; u < 8; u++) {
            int c = u * 32 + lane;
            float wv = W1[(size_t)n * 256 + c] * ln_ff_g[c];
            W1p[(size_t)n * 256 + c] = wv;
            s1 += wv;
            s2 += W1[(size_t)n * 256 + c] * ln_ff_b[c];
        }
        s1 = warp_sum(s1); s2 = warp_sum(s2);
        if (lane == 0) { S1m[n] = s1; S2m[n] = s2; }
    } else {
        int idx = (blk - 224) * 256 + threadIdx.x;
        int d = idx & 255;
        slots[idx] = mu[d] + __expf(ls[d]) * noise[idx];
    }
}

// ---------------------------------------------------------------------------
// KV GEMM: C_bf16[32768, 512] = LN(x) @ [W'k;W'v]^T.
// BM=128 BN=64 BK=32, 2 CTAs/SM; bf16 m16n8k16; LN-fold epilogue, bf16 out.
// grid (8, 256). warps: m0=(w>>2)*64, n0=(w&3)*16.
// ---------------------------------------------------------------------------
__global__ __launch_bounds__(256, 2) void kv_mma_kernel(
    const float* __restrict__ x, const __nv_bfloat16* __restrict__ wb,
    const float* __restrict__ S1, const float* __restrict__ S2,
    __nv_bfloat16* __restrict__ C) {
    __shared__ uint32_t As[128][20];
    __shared__ uint32_t Bs[64][20];
    __shared__ float rowm[128], rowr[128];
    int t = threadIdx.x;
    int bm = blockIdx.y * 128, bn = blockIdx.x * 64;
    int w = t >> 5, lane = t & 31;
    int m0 = (w >> 2) * 64, n0 = (w & 3) * 16;
    int g = lane >> 2, tig = lane & 3;
    float acc[4][2][4];
#pragma unroll
    for (int a = 0; a < 4; a++)
#pragma unroll
        for (int bq = 0; bq < 2; bq++)
#pragma unroll
            for (int c = 0; c < 4; c++) acc[a][bq][c] = 0.f;

    int lm = t >> 3;            // 0..31
    int lkf = (t & 7) * 4;
    int lku = (t & 7) * 2;

    float4 ar[4]; uint2 br[2];
    float sA[4] = {0.f, 0.f, 0.f, 0.f}, s2A[4] = {0.f, 0.f, 0.f, 0.f};
#pragma unroll
    for (int r = 0; r < 4; r++)
        ar[r] = *(const float4*)(x + (size_t)(bm + r * 32 + lm) * 256 + lkf);
#pragma unroll
    for (int r = 0; r < 2; r++)
        br[r] = *(const uint2*)(wb + (size_t)(bn + r * 32 + lm) * 256 + lkf);

    for (int it = 0; it < 8; it++) {
#pragma unroll
        for (int r = 0; r < 4; r++) {
            sA[r] += ar[r].x + ar[r].y + ar[r].z + ar[r].w;
            s2A[r] += ar[r].x * ar[r].x + ar[r].y * ar[r].y + ar[r].z * ar[r].z + ar[r].w * ar[r].w;
        }
        __syncthreads();
#pragma unroll
        for (int r = 0; r < 4; r++) {
            int m = r * 32 + lm;
            __nv_bfloat162 p0 = __floats2bfloat162_rn(ar[r].x, ar[r].y);
            __nv_bfloat162 p1 = __floats2bfloat162_rn(ar[r].z, ar[r].w);
            As[m][lku + 0] = *(uint32_t*)&p0;
            As[m][lku + 1] = *(uint32_t*)&p1;
        }
#pragma unroll
        for (int r = 0; r < 2; r++) {
            int m = r * 32 + lm;
            Bs[m][lku + 0] = br[r].x;
            Bs[m][lku + 1] = br[r].y;
        }
        __syncthreads();
        if (it < 7) {
            int c = (it + 1) * 32 + lkf;
#pragma unroll
            for (int r = 0; r < 4; r++)
                ar[r] = *(const float4*)(x + (size_t)(bm + r * 32 + lm) * 256 + c);
#pragma unroll
            for (int r = 0; r < 2; r++)
                br[r] = *(const uint2*)(wb + (size_t)(bn + r * 32 + lm) * 256 + c);
        }
#pragma unroll
        for (int ks = 0; ks < 2; ks++) {
            unsigned a[4][4], b[2][2];
#pragma unroll
            for (int mt = 0; mt < 4; mt++) {
                int mr = m0 + mt * 16 + g;
                a[mt][0] = As[mr][ks * 8 + tig];
                a[mt][1] = As[mr + 8][ks * 8 + tig];
                a[mt][2] = As[mr][ks * 8 + tig + 4];
                a[mt][3] = As[mr + 8][ks * 8 + tig + 4];
            }
#pragma unroll
            for (int nt = 0; nt < 2; nt++) {
                int nr = n0 + nt * 8 + g;
                b[nt][0] = Bs[nr][ks * 8 + tig];
                b[nt][1] = Bs[nr][ks * 8 + tig + 4];
            }
#pragma unroll
            for (int mt = 0; mt < 4; mt++)
#pragma unroll
                for (int nt = 0; nt < 2; nt++)
                    mma16(acc[mt][nt], a[mt], b[nt]);
        }
    }
#pragma unroll
    for (int r = 0; r < 4; r++) {
        float s = grp8_sum(sA[r]);
        float s2 = grp8_sum(s2A[r]);
        if ((t & 7) == 0) {
            float m = s * (1.0f / 256.0f);
            float var = s2 * (1.0f / 256.0f) - m * m;
            rowm[r * 32 + lm] = m;
            rowr[r * 32 + lm] = rsqrtf(var + 1e-5f);
        }
    }
    __syncthreads();
#pragma unroll
    for (int mt = 0; mt < 4; mt++)
#pragma unroll
        for (int nt = 0; nt < 2; nt++) {
            int lr = m0 + mt * 16 + g;
            int col = bn + n0 + nt * 8 + tig * 2;
            float s1a = S1[col], s1b = S1[col + 1], s2a = S2[col], s2b = S2[col + 1];
            float m0v = rowm[lr], r0v = rowr[lr];
            float m1v = rowm[lr + 8], r1v = rowr[lr + 8];
            __nv_bfloat162 o0 = __floats2bfloat162_rn(
                r0v * acc[mt][nt][0] - r0v * m0v * s1a + s2a,
                r0v * acc[mt][nt][1] - r0v * m0v * s1b + s2b);
            __nv_bfloat162 o1 = __floats2bfloat162_rn(
                r1v * acc[mt][nt][2] - r1v * m1v * s1a + s2a,
                r1v * acc[mt][nt][3] - r1v * m1v * s1b + s2b);
            *(uint32_t*)(C + (size_t)(bm + lr) * 512 + col) = *(uint32_t*)&o0;
            *(uint32_t*)(C + (size_t)(bm + lr + 8) * 512 + col) = *(uint32_t*)&o1;
        }
}

// ---------------------------------------------------------------------------
// gemm16: 16-row x NC-col tiles, 256 threads, register-prefetched BK=32.
// ---------------------------------------------------------------------------
template<int NC, bool LNF, bool RELU, bool ADDOUT, bool QSC>
__global__ __launch_bounds__(256) void gemm16_kernel(
    const float* __restrict__ A, const float* __restrict__ B,
    const float* __restrict__ S1, const float* __restrict__ S2,
    const float* __restrict__ bias, const float* __restrict__ addsrc,
    float* __restrict__ C, int N, int K) {
    constexpr int CPT = NC / 32;
    __shared__ float As[16][34];
    __shared__ float Bs[NC][34];
    __shared__ float rowm[16], rowr[16];
    int t = threadIdx.x;
    int bm = blockIdx.y * 16, bn = blockIdx.x * NC;
    if (LNF) {
        int w = t >> 5, lane = t & 31;
#pragma unroll
        for (int rr = 0; rr < 2; rr++) {
            int row = w * 2 + rr;
            const float* p = A + (size_t)(bm + row) * 256;
            float s = 0.f, s2 = 0.f;
#pragma unroll
            for (int u = 0; u < 8; u++) { float v = p[lane + u * 32]; s += v; s2 += v * v; }
            s = warp_sum(s); s2 = warp_sum(s2);
            if (lane == 0) {
                float m = s * (1.0f / 256.0f);
                float var = s2 * (1.0f / 256.0f) - m * m;
                rowm[row] = m; rowr[row] = rsqrtf(var + 1e-5f);
            }
        }
    }
    int ar = t >> 4, ak = (t & 15) * 2;
    int brr = t >> 3, bk = (t & 7) * 4;
    int tr = t >> 5, tc = t & 31;
    float acc[2][CPT];
#pragma unroll
    for (int r = 0; r < 2; r++)
#pragma unroll
        for (int c = 0; c < CPT; c++) acc[r][c] = 0.f;

    float2 pa = *(const float2*)(A + (size_t)(bm + ar) * K + ak);
    float4 pb[CPT];
#pragma unroll
    for (int c = 0; c < CPT; c++)
        pb[c] = *(const float4*)(B + (size_t)(bn + c * 32 + brr) * K + bk);

    int KT = K >> 5;
    for (int kt = 0; kt < KT; kt++) {
        __syncthreads();
        As[ar][ak] = pa.x; As[ar][ak + 1] = pa.y;
#pragma unroll
        for (int c = 0; c < CPT; c++) {
            Bs[c * 32 + brr][bk + 0] = pb[c].x; Bs[c * 32 + brr][bk + 1] = pb[c].y;
            Bs[c * 32 + brr][bk + 2] = pb[c].z; Bs[c * 32 + brr][bk + 3] = pb[c].w;
        }
        __syncthreads();
        if (kt + 1 < KT) {
            int k0 = (kt + 1) * 32;
            pa = *(const float2*)(A + (size_t)(bm + ar) * K + k0 + ak);
#pragma unroll
            for (int c = 0; c < CPT; c++)
                pb[c] = *(const float4*)(B + (size_t)(bn + c * 32 + brr) * K + k0 + bk);
        }
#pragma unroll
        for (int kk = 0; kk < 32; kk += 2) {
            float2 a0 = *(const float2*)&As[tr][kk];
            float2 a1 = *(const float2*)&As[tr + 8][kk];
#pragma unroll
            for (int c = 0; c < CPT; c++) {
                float2 b2 = *(const float2*)&Bs[tc + c * 32][kk];
                acc[0][c] += a0.x * b2.x + a0.y * b2.y;
                acc[1][c] += a1.x * b2.x + a1.y * b2.y;
            }
        }
    }
#pragma unroll
    for (int r = 0; r < 2; r++) {
        int lr = tr + r * 8;
        int row = bm + lr;
#pragma unroll
        for (int c = 0; c < CPT; c++) {
            int col = bn + c * 32 + tc;
            float v = acc[r][c];
            if (LNF) { float m = rowm[lr], rs = rowr[lr]; v = rs * v - rs * m * S1[col] + S2[col]; }
            if (bias) v += bias[col];
            if (RELU) v = fmaxf(v, 0.f);
            if (QSC) v *= SCALE_F;
            if (ADDOUT) v += addsrc[(size_t)row * N + col];
            C[(size_t)row * N + col] = v;
        }
    }
}

// ---------------------------------------------------------------------------
// attention: dots + softmax over slots + updates partials. bf16 kv.
// grid (32 batches, 16 j-chunks of 64).
// ---------------------------------------------------------------------------
__global__ __launch_bounds__(256) void attn2_kernel(
    const float* __restrict__ qbuf, const __nv_bfloat16* __restrict__ kv,
    float* __restrict__ updp, float* __restrict__ rsp) {
    __shared__ __align__(16) float qs[8][256];
    __shared__ float attn_s[64][9];
    __shared__ float rswarp[8][8];
    int b = blockIdx.x, jc = blockIdx.y;
    int t = threadIdx.x, w = t >> 5, lane = t & 31;

#pragma unroll
    for (int u = 0; u < 8; u++)
        qs[u][t] = qbuf[(size_t)(b * 8 + u) * 256 + t];
    __syncthreads();

    // dots + softmax: warp w handles jl = w + 8*jj. bf16 k rows, prefetched.
    float rsa = 0.f;
    {
        const uint32_t* kbase = (const uint32_t*)(kv + ((size_t)b * NTOK + jc * 64) * 512);
        uint32_t kr0[4], kr1[4];
#pragma unroll
        for (int u = 0; u < 4; u++) kr0[u] = kbase[(size_t)w * 256 + u * 32 + lane];
#pragma unroll 1
        for (int jj = 0; jj < 8; jj++) {
            int jl = w + jj * 8;
            if (jj < 7) {
#pragma unroll
                for (int u = 0; u < 4; u++)
                    kr1[u] = kbase[(size_t)(jl + 8) * 256 + u * 32 + lane];
            }
            float2 kf[4];
#pragma unroll
            for (int u = 0; u < 4; u++)
                kf[u] = __bfloat1622float2(*(__nv_bfloat162*)&kr0[u]);
            float dv[8];
#pragma unroll
            for (int i = 0; i < 8; i++) {
                float p = 0.f;
#pragma unroll
                for (int u = 0; u < 4; u++) {
                    float2 q2 = *(const float2*)&qs[i][(lane + u * 32) * 2];
                    p += q2.x * kf[u].x + q2.y * kf[u].y;
                }
                dv[i] = warp_sum(p);
            }
            float mx = dv[0];
#pragma unroll
            for (int i = 1; i < 8; i++) mx = fmaxf(mx, dv[i]);
            float se = 0.f, ev[8];
#pragma unroll
            for (int i = 0; i < 8; i++) { ev[i] = __expf(dv[i] - mx); se += ev[i]; }
            float inv = 1.0f / se;
            float my = 0.f;
#pragma unroll
            for (int i = 0; i < 8; i++) {
                float a = ev[i] * inv + EPS_F;
                if (lane == i) my = a;
            }
            if (lane < 8) { attn_s[jl][lane] = my; rsa += my; }
#pragma unroll
            for (int u = 0; u < 4; u++) kr0[u] = kr1[u];
        }
    }
    if (lane < 8) rswarp[w][lane] = rsa;
    __syncthreads();

    // updates: thread t = value col; 8-wide batched bf16 v loads.
    {
        float uacc[8];
#pragma unroll
        for (int i = 0; i < 8; i++) uacc[i] = 0.f;
        const __nv_bfloat16* vbase = kv + ((size_t)b * NTOK + jc * 64) * 512 + 256 + t;
#pragma unroll 1
        for (int j0 = 0; j0 < 64; j0 += 8) {
            float va[8];
#pragma unroll
            for (int r = 0; r < 8; r++) va[r] = __bfloat162float(vbase[(size_t)(j0 + r) * 512]);
#pragma unroll
            for (int r = 0; r < 8; r++)
#pragma unroll
                for (int i = 0; i < 8; i++) uacc[i] += attn_s[j0 + r][i] * va[r];
        }
#pragma unroll
        for (int i = 0; i < 8; i++)
            updp[((size_t)jc * SROWS + b * 8 + i) * 256 + t] = uacc[i];
        if (t < 8) {
            float r = 0.f;
#pragma unroll
            for (int ww = 0; ww < 8; ww++) r += rswarp[ww][t];
            rsp[jc * SROWS + b * 8 + t] = r;
        }
    }
}

// ---------------------------------------------------------------------------
// GRU, 16x32 units, updp reduction inline. grid (8, 16) = 128 blocks.
// ---------------------------------------------------------------------------
__global__ __launch_bounds__(256) void gru16_kernel(
    const float* __restrict__ updp, const float* __restrict__ rsp,
    const float* __restrict__ slots,
    const float* __restrict__ wih, const float* __restrict__ whh,
    const float* __restrict__ bih, const float* __restrict__ bhh,
    float* __restrict__ out) {
    __shared__ float Au[16][34], Ah[16][34];
    __shared__ float Bg[6][32][34];
    __shared__ float invrs[16];
    int t = threadIdx.x;
    int bm = blockIdx.y * 16, bn = blockIdx.x * 32;
    if (t < 16) {
        float rs = 0.f;
#pragma unroll
        for (int p = 0; p < NCHUNK; p++) rs += rsp[p * 256 + bm + t];
        invrs[t] = 1.0f / rs;
    }
    int ar = t >> 4, ak = (t & 15) * 2;
    int brr = t >> 3, bk = (t & 7) * 4;
    int tr = t >> 5, tc = t & 31;
    float acc[6][2];
#pragma unroll
    for (int g = 0; g < 6; g++) { acc[g][0] = 0.f; acc[g][1] = 0.f; }

    for (int kt = 0; kt < 8; kt++) {
        int k0 = kt * 32;
        __syncthreads();
        {
            size_t base = (size_t)(bm + ar) * 256 + k0 + ak;
            float sx = 0.f, sy = 0.f;
#pragma unroll
            for (int p = 0; p < NCHUNK; p++) {
                float2 v = *(const float2*)(updp + (size_t)p * 65536 + base);
                sx += v.x; sy += v.y;
            }
            float iv = invrs[ar];
            Au[ar][ak] = sx * iv; Au[ar][ak + 1] = sy * iv;
            float2 h2 = *(const float2*)(slots + base);
            Ah[ar][ak] = h2.x; Ah[ar][ak + 1] = h2.y;
#pragma unroll
            for (int g = 0; g < 6; g++) {
                const float* W = (g < 3) ? wih : whh;
                float4 w4 = *(const float4*)(W + (size_t)((g % 3) * 256 + bn + brr) * 256 + k0 + bk);
                Bg[g][brr][bk + 0] = w4.x; Bg[g][brr][bk + 1] = w4.y;
                Bg[g][brr][bk + 2] = w4.z; Bg[g][brr][bk + 3] = w4.w;
            }
        }
        __syncthreads();
#pragma unroll
        for (int kk = 0; kk < 32; kk += 2) {
            float2 u0 = *(const float2*)&Au[tr][kk];
            float2 u1 = *(const float2*)&Au[tr + 8][kk];
            float2 h0 = *(const float2*)&Ah[tr][kk];
            float2 h1v = *(const float2*)&Ah[tr + 8][kk];
#pragma unroll
            for (int g = 0; g < 6; g++) {
                float2 b2 = *(const float2*)&Bg[g][tc][kk];
                if (g < 3) {
                    acc[g][0] += u0.x * b2.x + u0.y * b2.y;
                    acc[g][1] += u1.x * b2.x + u1.y * b2.y;
                } else {
                    acc[g][0] += h0.x * b2.x + h0.y * b2.y;
                    acc[g][1] += h1v.x * b2.x + h1v.y * b2.y;
                }
            }
        }
    }
    int col = bn + tc;
#pragma unroll
    for (int r = 0; r < 2; r++) {
        int row = bm + tr + r * 8;
        float ir = acc[0][r] + bih[col];
        float iz = acc[1][r] + bih[col + 256];
        float in_ = acc[2][r] + bih[col + 512];
        float hr = acc[3][r] + bhh[col];
        float hz = acc[4][r] + bhh[col + 256];
        float hn = acc[5][r] + bhh[col + 512];
        float rg = sigmoidf_(ir + hr);
        float z = sigmoidf_(iz + hz);
        float nn = tanhf(in_ + rg * hn);
        float h = slots[(size_t)row * 256 + col];
        out[(size_t)row * 256 + col] = (1.0f - z) * nn + z * h;
    }
}

extern "C" void kernel_launch(void* const* d_in, const int* in_sizes, int n_in,
                              void* d_out, int out_size) {
    const float* inputs    = (const float*)d_in[0];
    const float* noise     = (const float*)d_in[1];
    const float* slots_mu  = (const float*)d_in[2];
    const float* slots_ls  = (const float*)d_in[3];
    const float* Wq        = (const float*)d_in[4];
    const float* Wk        = (const float*)d_in[5];
    const float* Wv        = (const float*)d_in[6];
    const float* gru_wih   = (const float*)d_in[7];
    const float* gru_whh   = (const float*)d_in[8];
    const float* gru_bih   = (const float*)d_in[9];
    const float* gru_bhh   = (const float*)d_in[10];
    const float* mlp_w1    = (const float*)d_in[11];
    const float* mlp_b1    = (const float*)d_in[12];
    const float* mlp_w2    = (const float*)d_in[13];
    const float* mlp_b2    = (const float*)d_in[14];
    const float* ln_in_g   = (const float*)d_in[15];
    const float* ln_in_b   = (const float*)d_in[16];
    const float* ln_s_g    = (const float*)d_in[17];
    const float* ln_s_b    = (const float*)d_in[18];
    const float* ln_ff_g   = (const float*)d_in[19];
    const float* ln_ff_b   = (const float*)d_in[20];

    float* S = nullptr;
    cudaGetSymbolAddress((void**)&S, g_scratch);
    __nv_bfloat16* wb = nullptr;
    cudaGetSymbolAddress((void**)&wb, g_wb);
    __nv_bfloat16* kv = (__nv_bfloat16*)(S + OFF_KV);
    float* slots = S + OFF_SLOTS;
    float* gbuf  = S + OFF_GBUF;
    float* qbuf  = S + OFF_Q;
    float* h1    = S + OFF_H1;
    float* updp  = S + OFF_UPDP;
    float* rsp   = S + OFF_RSP;
    float* S1kv  = S + OFF_S1KV;
    float* S2kv  = S + OFF_S2KV;
    float* Wqp   = S + OFF_WQP;
    float* S1q   = S + OFF_S1Q;
    float* S2q   = S + OFF_S2Q;
    float* W1p   = S + OFF_W1P;
    float* S1m   = S + OFF_S1M;
    float* S2m   = S + OFF_S2M;

    // 0: all preps + slot init
    setup_kernel<<<480, 256>>>(Wk, Wv, ln_in_g, ln_in_b, wb, S1kv, S2kv,
                               Wq, ln_s_g, ln_s_b, Wqp, S1q, S2q,
                               mlp_w1, ln_ff_g, ln_ff_b, W1p, S1m, S2m,
                               slots_mu, slots_ls, noise, slots);
    // 1: KV projection (bf16 out, 2 CTAs/SM)
    kv_mma_kernel<<<dim3(8, 256), 256>>>(inputs, wb, S1kv, S2kv, kv);

    for (int it = 0; it < ITERS; it++) {
        // q = LN(slots)@W'q * SCALE   (launch 2 on it0)
        gemm16_kernel<32, true, false, false, true><<<dim3(8, 16), 256>>>(
            slots, Wqp, S1q, S2q, nullptr, nullptr, qbuf, 256, 256);
        // attn partials                (launch 3 on it0 -> profiled)
        attn2_kernel<<<dim3(32, NCHUNK), 256>>>(qbuf, kv, updp, rsp);
        // GRU (updp reduce inline)
        gru16_kernel<<<dim3(8, 16), 256>>>(updp, rsp, slots,
            gru_wih, gru_whh, gru_bih, gru_bhh, gbuf);
        // mlp1 = relu(LN(gbuf)@W'1 + b1)
        gemm16_kernel<64, true, true, false, false><<<dim3(16, 16), 256>>>(
            gbuf, W1p, S1m, S2m, mlp_b1, nullptr, h1, 1024, 256);
        // mlp2 = h1@W2 + b2 + gbuf
        float* outp = (it == ITERS - 1) ? (float*)d_out : slots;
        gemm16_kernel<32, false, false, true, false><<<dim3(8, 16), 256>>>(
            h1, mlp_w2, nullptr, nullptr, mlp_b2, gbuf, outp, 256, 1024);
    }
}

// round 14
// speedup vs baseline: 2.1883x; 1.1330x over previous
#include <cuda_runtime.h>
#include <cuda_bf16.h>
#include <math.h>
#include <cstdint>

// ---------------------------------------------------------------------------
// SlotAttention: b=32, n=1024, c=256, d=256, S=8 slots, 3 iters.
// KV: bf16 m16n8k16 mma.sync, bf16 kv storage.
// attn: dots via tensor-core mma + lane-parallel softmax; float4 attn reads.
// ---------------------------------------------------------------------------
#define NTOK 1024
#define ITERS 3
#define TOKROWS 32768
#define SROWS 256
#define SCALE_F 0.0625f
#define EPS_F 1e-8f
#define NCHUNK 16               // attn j-chunks of 64

// scratch arena (floats)
#define OFF_KV     0                                  // bf16[32768*512]
#define OFF_SLOTS  (OFF_KV + TOKROWS*256)
#define OFF_GBUF   (OFF_SLOTS + SROWS*256)
#define OFF_Q      (OFF_GBUF + SROWS*256)
#define OFF_H1     (OFF_Q + SROWS*256)                // 256*1024
#define OFF_UPDP   (OFF_H1 + SROWS*1024)              // 16*256*256
#define OFF_RSP    (OFF_UPDP + NCHUNK*SROWS*256)      // 16*256
#define OFF_S1KV   (OFF_RSP + NCHUNK*SROWS)           // 512
#define OFF_S2KV   (OFF_S1KV + 512)
#define OFF_WQP    (OFF_S2KV + 512)                   // 256*256 row-major
#define OFF_S1Q    (OFF_WQP + 256*256)
#define OFF_S2Q    (OFF_S1Q + 256)
#define OFF_W1P    (OFF_S2Q + 256)                    // 1024*256
#define OFF_S1M    (OFF_W1P + 1024*256)
#define OFF_S2M    (OFF_S1M + 1024)
#define SCRATCH_FLOATS (OFF_S2M + 1024)

__device__ __align__(16) float g_scratch[SCRATCH_FLOATS];
__device__ __align__(16) __nv_bfloat16 g_wb[512 * 256];

__device__ __forceinline__ float warp_sum(float v) {
#pragma unroll
    for (int o = 16; o > 0; o >>= 1) v += __shfl_xor_sync(0xffffffffu, v, o);
    return v;
}
__device__ __forceinline__ float grp8_sum(float v) {
    v += __shfl_xor_sync(0xffffffffu, v, 4);
    v += __shfl_xor_sync(0xffffffffu, v, 2);
    v += __shfl_xor_sync(0xffffffffu, v, 1);
    return v;
}
__device__ __forceinline__ float sigmoidf_(float x) { return 1.0f / (1.0f + __expf(-x)); }

__device__ __forceinline__ void mma16(float* d, const unsigned* a, const unsigned* b) {
    asm volatile("mma.sync.aligned.m16n8k16.row.col.f32.bf16.bf16.f32 "
        "{%0,%1,%2,%3}, {%4,%5,%6,%7}, {%8,%9}, {%0,%1,%2,%3};"
        : "+f"(d[0]), "+f"(d[1]), "+f"(d[2]), "+f"(d[3])
        : "r"(a[0]), "r"(a[1]), "r"(a[2]), "r"(a[3]), "r"(b[0]), "r"(b[1]));
}

// ---------------------------------------------------------------------------
// setup: all weight preps + slot init in ONE kernel (grid 480).
// ---------------------------------------------------------------------------
__global__ void setup_kernel(
    const float* __restrict__ Wk, const float* __restrict__ Wv,
    const float* __restrict__ ln_in_g, const float* __restrict__ ln_in_b,
    __nv_bfloat16* __restrict__ wb, float* __restrict__ S1kv, float* __restrict__ S2kv,
    const float* __restrict__ Wq, const float* __restrict__ ln_s_g, const float* __restrict__ ln_s_b,
    float* __restrict__ Wqp, float* __restrict__ S1q, float* __restrict__ S2q,
    const float* __restrict__ W1, const float* __restrict__ ln_ff_g, const float* __restrict__ ln_ff_b,
    float* __restrict__ W1p, float* __restrict__ S1m, float* __restrict__ S2m,
    const float* __restrict__ mu, const float* __restrict__ ls,
    const float* __restrict__ noise, float* __restrict__ slots) {
    int blk = blockIdx.x;
    int w = threadIdx.x >> 5, lane = threadIdx.x & 31;
    if (blk < 64) {
        int n = blk * 8 + w;
        const float* src = (n < 256) ? Wk + (size_t)n * 256 : Wv + (size_t)(n - 256) * 256;
        float s1 = 0.f, s2 = 0.f;
#pragma unroll
        for (int u = 0; u < 8; u++) {
            int c = u * 32 + lane;
            __nv_bfloat16 bf = __float2bfloat16(src[c] * ln_in_g[c]);
            wb[(size_t)n * 256 + c] = bf;
            s1 += __bfloat162float(bf);
            s2 += src[c] * ln_in_b[c];
        }
        s1 = warp_sum(s1); s2 = warp_sum(s2);
        if (lane == 0) { S1kv[n] = s1; S2kv[n] = s2; }
    } else if (blk < 96) {
        int n = (blk - 64) * 8 + w;
        float s1 = 0.f, s2 = 0.f;
#pragma unroll
        for (int u = 0; u < 8; u++) {
            int c = u * 32 + lane;
            float wv = Wq[(size_t)n * 256 + c] * ln_s_g[c];
            Wqp[(size_t)n * 256 + c] = wv;
            s1 += wv;
            s2 += Wq[(size_t)n * 256 + c] * ln_s_b[c];
        }
        s1 = warp_sum(s1); s2 = warp_sum(s2);
        if (lane == 0) { S1q[n] = s1; S2q[n] = s2; }
    } else if (blk < 224) {
        int n = (blk - 96) * 8 + w;
        float s1 = 0.f, s2 = 0.f;
#pragma unroll
        for (int u = 0; u < 8; u++) {
            int c = u * 32 + lane;
            float wv = W1[(size_t)n * 256 + c] * ln_ff_g[c];
            W1p[(size_t)n * 256 + c] = wv;
            s1 += wv;
            s2 += W1[(size_t)n * 256 + c] * ln_ff_b[c];
        }
        s1 = warp_sum(s1); s2 = warp_sum(s2);
        if (lane == 0) { S1m[n] = s1; S2m[n] = s2; }
    } else {
        int idx = (blk - 224) * 256 + threadIdx.x;
        int d = idx & 255;
        slots[idx] = mu[d] + __expf(ls[d]) * noise[idx];
    }
}

// ---------------------------------------------------------------------------
// KV GEMM: C_bf16[32768, 512] = LN(x) @ [W'k;W'v]^T.
// BM=128 BN=64 BK=32, 2 CTAs/SM; bf16 m16n8k16; LN-fold epilogue, bf16 out.
// ---------------------------------------------------------------------------
__global__ __launch_bounds__(256, 2) void kv_mma_kernel(
    const float* __restrict__ x, const __nv_bfloat16* __restrict__ wb,
    const float* __restrict__ S1, const float* __restrict__ S2,
    __nv_bfloat16* __restrict__ C) {
    __shared__ uint32_t As[128][20];
    __shared__ uint32_t Bs[64][20];
    __shared__ float rowm[128], rowr[128];
    int t = threadIdx.x;
    int bm = blockIdx.y * 128, bn = blockIdx.x * 64;
    int w = t >> 5, lane = t & 31;
    int m0 = (w >> 2) * 64, n0 = (w & 3) * 16;
    int g = lane >> 2, tig = lane & 3;
    float acc[4][2][4];
#pragma unroll
    for (int a = 0; a < 4; a++)
#pragma unroll
        for (int bq = 0; bq < 2; bq++)
#pragma unroll
            for (int c = 0; c < 4; c++) acc[a][bq][c] = 0.f;

    int lm = t >> 3;
    int lkf = (t & 7) * 4;
    int lku = (t & 7) * 2;

    float4 ar[4]; uint2 br[2];
    float sA[4] = {0.f, 0.f, 0.f, 0.f}, s2A[4] = {0.f, 0.f, 0.f, 0.f};
#pragma unroll
    for (int r = 0; r < 4; r++)
        ar[r] = *(const float4*)(x + (size_t)(bm + r * 32 + lm) * 256 + lkf);
#pragma unroll
    for (int r = 0; r < 2; r++)
        br[r] = *(const uint2*)(wb + (size_t)(bn + r * 32 + lm) * 256 + lkf);

    for (int it = 0; it < 8; it++) {
#pragma unroll
        for (int r = 0; r < 4; r++) {
            sA[r] += ar[r].x + ar[r].y + ar[r].z + ar[r].w;
            s2A[r] += ar[r].x * ar[r].x + ar[r].y * ar[r].y + ar[r].z * ar[r].z + ar[r].w * ar[r].w;
        }
        __syncthreads();
#pragma unroll
        for (int r = 0; r < 4; r++) {
            int m = r * 32 + lm;
            __nv_bfloat162 p0 = __floats2bfloat162_rn(ar[r].x, ar[r].y);
            __nv_bfloat162 p1 = __floats2bfloat162_rn(ar[r].z, ar[r].w);
            As[m][lku + 0] = *(uint32_t*)&p0;
            As[m][lku + 1] = *(uint32_t*)&p1;
        }
#pragma unroll
        for (int r = 0; r < 2; r++) {
            int m = r * 32 + lm;
            Bs[m][lku + 0] = br[r].x;
            Bs[m][lku + 1] = br[r].y;
        }
        __syncthreads();
        if (it < 7) {
            int c = (it + 1) * 32 + lkf;
#pragma unroll
            for (int r = 0; r < 4; r++)
                ar[r] = *(const float4*)(x + (size_t)(bm + r * 32 + lm) * 256 + c);
#pragma unroll
            for (int r = 0; r < 2; r++)
                br[r] = *(const uint2*)(wb + (size_t)(bn + r * 32 + lm) * 256 + c);
        }
#pragma unroll
        for (int ks = 0; ks < 2; ks++) {
            unsigned a[4][4], b[2][2];
#pragma unroll
            for (int mt = 0; mt < 4; mt++) {
                int mr = m0 + mt * 16 + g;
                a[mt][0] = As[mr][ks * 8 + tig];
                a[mt][1] = As[mr + 8][ks * 8 + tig];
                a[mt][2] = As[mr][ks * 8 + tig + 4];
                a[mt][3] = As[mr + 8][ks * 8 + tig + 4];
            }
#pragma unroll
            for (int nt = 0; nt < 2; nt++) {
                int nr = n0 + nt * 8 + g;
                b[nt][0] = Bs[nr][ks * 8 + tig];
                b[nt][1] = Bs[nr][ks * 8 + tig + 4];
            }
#pragma unroll
            for (int mt = 0; mt < 4; mt++)
#pragma unroll
                for (int nt = 0; nt < 2; nt++)
                    mma16(acc[mt][nt], a[mt], b[nt]);
        }
    }
#pragma unroll
    for (int r = 0; r < 4; r++) {
        float s = grp8_sum(sA[r]);
        float s2 = grp8_sum(s2A[r]);
        if ((t & 7) == 0) {
            float m = s * (1.0f / 256.0f);
            float var = s2 * (1.0f / 256.0f) - m * m;
            rowm[r * 32 + lm] = m;
            rowr[r * 32 + lm] = rsqrtf(var + 1e-5f);
        }
    }
    __syncthreads();
#pragma unroll
    for (int mt = 0; mt < 4; mt++)
#pragma unroll
        for (int nt = 0; nt < 2; nt++) {
            int lr = m0 + mt * 16 + g;
            int col = bn + n0 + nt * 8 + tig * 2;
            float s1a = S1[col], s1b = S1[col + 1], s2a = S2[col], s2b = S2[col + 1];
            float m0v = rowm[lr], r0v = rowr[lr];
            float m1v = rowm[lr + 8], r1v = rowr[lr + 8];
            __nv_bfloat162 o0 = __floats2bfloat162_rn(
                r0v * acc[mt][nt][0] - r0v * m0v * s1a + s2a,
                r0v * acc[mt][nt][1] - r0v * m0v * s1b + s2b);
            __nv_bfloat162 o1 = __floats2bfloat162_rn(
                r1v * acc[mt][nt][2] - r1v * m1v * s1a + s2a,
                r1v * acc[mt][nt][3] - r1v * m1v * s1b + s2b);
            *(uint32_t*)(C + (size_t)(bm + lr) * 512 + col) = *(uint32_t*)&o0;
            *(uint32_t*)(C + (size_t)(bm + lr + 8) * 512 + col) = *(uint32_t*)&o1;
        }
}

// ---------------------------------------------------------------------------
// gemm16: 16-row x NC-col tiles, 256 threads, register-prefetched BK=32.
// ---------------------------------------------------------------------------
template<int NC, bool LNF, bool RELU, bool ADDOUT, bool QSC>
__global__ __launch_bounds__(256) void gemm16_kernel(
    const float* __restrict__ A, const float* __restrict__ B,
    const float* __restrict__ S1, const float* __restrict__ S2,
    const float* __restrict__ bias, const float* __restrict__ addsrc,
    float* __restrict__ C, int N, int K) {
    constexpr int CPT = NC / 32;
    __shared__ float As[16][34];
    __shared__ float Bs[NC][34];
    __shared__ float rowm[16], rowr[16];
    int t = threadIdx.x;
    int bm = blockIdx.y * 16, bn = blockIdx.x * NC;
    if (LNF) {
        int w = t >> 5, lane = t & 31;
#pragma unroll
        for (int rr = 0; rr < 2; rr++) {
            int row = w * 2 + rr;
            const float* p = A + (size_t)(bm + row) * 256;
            float s = 0.f, s2 = 0.f;
#pragma unroll
            for (int u = 0; u < 8; u++) { float v = p[lane + u * 32]; s += v; s2 += v * v; }
            s = warp_sum(s); s2 = warp_sum(s2);
            if (lane == 0) {
                float m = s * (1.0f / 256.0f);
                float var = s2 * (1.0f / 256.0f) - m * m;
                rowm[row] = m; rowr[row] = rsqrtf(var + 1e-5f);
            }
        }
    }
    int ar = t >> 4, ak = (t & 15) * 2;
    int brr = t >> 3, bk = (t & 7) * 4;
    int tr = t >> 5, tc = t & 31;
    float acc[2][CPT];
#pragma unroll
    for (int r = 0; r < 2; r++)
#pragma unroll
        for (int c = 0; c < CPT; c++) acc[r][c] = 0.f;

    float2 pa = *(const float2*)(A + (size_t)(bm + ar) * K + ak);
    float4 pb[CPT];
#pragma unroll
    for (int c = 0; c < CPT; c++)
        pb[c] = *(const float4*)(B + (size_t)(bn + c * 32 + brr) * K + bk);

    int KT = K >> 5;
    for (int kt = 0; kt < KT; kt++) {
        __syncthreads();
        As[ar][ak] = pa.x; As[ar][ak + 1] = pa.y;
#pragma unroll
        for (int c = 0; c < CPT; c++) {
            Bs[c * 32 + brr][bk + 0] = pb[c].x; Bs[c * 32 + brr][bk + 1] = pb[c].y;
            Bs[c * 32 + brr][bk + 2] = pb[c].z; Bs[c * 32 + brr][bk + 3] = pb[c].w;
        }
        __syncthreads();
        if (kt + 1 < KT) {
            int k0 = (kt + 1) * 32;
            pa = *(const float2*)(A + (size_t)(bm + ar) * K + k0 + ak);
#pragma unroll
            for (int c = 0; c < CPT; c++)
                pb[c] = *(const float4*)(B + (size_t)(bn + c * 32 + brr) * K + k0 + bk);
        }
#pragma unroll
        for (int kk = 0; kk < 32; kk += 2) {
            float2 a0 = *(const float2*)&As[tr][kk];
            float2 a1 = *(const float2*)&As[tr + 8][kk];
#pragma unroll
            for (int c = 0; c < CPT; c++) {
                float2 b2 = *(const float2*)&Bs[tc + c * 32][kk];
                acc[0][c] += a0.x * b2.x + a0.y * b2.y;
                acc[1][c] += a1.x * b2.x + a1.y * b2.y;
            }
        }
    }
#pragma unroll
    for (int r = 0; r < 2; r++) {
        int lr = tr + r * 8;
        int row = bm + lr;
#pragma unroll
        for (int c = 0; c < CPT; c++) {
            int col = bn + c * 32 + tc;
            float v = acc[r][c];
            if (LNF) { float m = rowm[lr], rs = rowr[lr]; v = rs * v - rs * m * S1[col] + S2[col]; }
            if (bias) v += bias[col];
            if (RELU) v = fmaxf(v, 0.f);
            if (QSC) v *= SCALE_F;
            if (ADDOUT) v += addsrc[(size_t)row * N + col];
            C[(size_t)row * N + col] = v;
        }
    }
}

// ---------------------------------------------------------------------------
// attention: dots via m16n8k16 mma (q bf16 in smem, k bf16 from gmem),
// lane-parallel softmax over slots, float4 attn reads in updates.
// grid (32 batches, 16 j-chunks of 64).
// ---------------------------------------------------------------------------
__global__ __launch_bounds__(256) void attn2_kernel(
    const float* __restrict__ qbuf, const __nv_bfloat16* __restrict__ kv,
    float* __restrict__ updp, float* __restrict__ rsp) {
    __shared__ uint32_t qs[8][132];          // bf16x2 pairs, row = slot, col = k-pair
    __shared__ __align__(16) float attn_s[64][12];
    __shared__ float rswarp[8][8];
    int b = blockIdx.x, jc = blockIdx.y;
    int t = threadIdx.x, w = t >> 5, lane = t & 31;
    int g = lane >> 2, tig = lane & 3;

    // stage q as bf16 pairs: thread t -> slot row t>>5, 8 floats at (t&31)*8
    {
        int row = t >> 5, c8 = (t & 31) * 8;
        const float* qrow = qbuf + (size_t)(b * 8 + row) * 256 + c8;
        float4 f0 = *(const float4*)(qrow);
        float4 f1 = *(const float4*)(qrow + 4);
        __nv_bfloat162 p0 = __floats2bfloat162_rn(f0.x, f0.y);
        __nv_bfloat162 p1 = __floats2bfloat162_rn(f0.z, f0.w);
        __nv_bfloat162 p2 = __floats2bfloat162_rn(f1.x, f1.y);
        __nv_bfloat162 p3 = __floats2bfloat162_rn(f1.z, f1.w);
        int c4 = c8 >> 1;
        qs[row][c4 + 0] = *(uint32_t*)&p0;
        qs[row][c4 + 1] = *(uint32_t*)&p1;
        qs[row][c4 + 2] = *(uint32_t*)&p2;
        qs[row][c4 + 3] = *(uint32_t*)&p3;
    }
    __syncthreads();

    // dots mma: warp w -> j-tile [w*8, w*8+8); output lane (g,tig):
    // c[0] = dot(slot g, j = w*8 + tig*2), c[1] = (slot g, j = w*8 + tig*2 + 1)
    {
        const uint32_t* kbase = (const uint32_t*)(kv + ((size_t)b * NTOK + jc * 64 + w * 8) * 512);
        float c[4] = {0.f, 0.f, 0.f, 0.f};
        uint32_t b0 = kbase[(size_t)g * 256 + tig];
        uint32_t b1 = kbase[(size_t)g * 256 + tig + 4];
#pragma unroll
        for (int ks = 0; ks < 16; ks++) {
            unsigned a[4], bfr[2];
            a[0] = qs[g][ks * 8 + tig];
            a[1] = 0u;
            a[2] = qs[g][ks * 8 + tig + 4];
            a[3] = 0u;
            bfr[0] = b0; bfr[1] = b1;
            if (ks < 15) {
                b0 = kbase[(size_t)g * 256 + (ks + 1) * 8 + tig];
                b1 = kbase[(size_t)g * 256 + (ks + 1) * 8 + tig + 4];
            }
            mma16(c, a, bfr);
        }
        // softmax over slots: reduce across lanes varying g (xor 4,8,16)
        float m0 = c[0], m1 = c[1];
#pragma unroll
        for (int o = 4; o <= 16; o <<= 1) {
            m0 = fmaxf(m0, __shfl_xor_sync(0xffffffffu, m0, o));
            m1 = fmaxf(m1, __shfl_xor_sync(0xffffffffu, m1, o));
        }
        float e0 = __expf(c[0] - m0), e1 = __expf(c[1] - m1);
        float s0 = e0, s1 = e1;
#pragma unroll
        for (int o = 4; o <= 16; o <<= 1) {
            s0 += __shfl_xor_sync(0xffffffffu, s0, o);
            s1 += __shfl_xor_sync(0xffffffffu, s1, o);
        }
        float a0 = e0 / s0 + EPS_F;
        float a1 = e1 / s1 + EPS_F;
        attn_s[w * 8 + tig * 2][g] = a0;
        attn_s[w * 8 + tig * 2 + 1][g] = a1;
        // per-slot row sums over this warp's 8 j's: reduce across tig (xor 1,2)
        float rsa = a0 + a1;
        rsa += __shfl_xor_sync(0xffffffffu, rsa, 1);
        rsa += __shfl_xor_sync(0xffffffffu, rsa, 2);
        if (tig == 0) rswarp[w][g] = rsa;
    }
    __syncthreads();

    // updates: thread t = value col; 8-wide batched bf16 v loads, float4 attn.
    {
        float uacc[8];
#pragma unroll
        for (int i = 0; i < 8; i++) uacc[i] = 0.f;
        const __nv_bfloat16* vbase = kv + ((size_t)b * NTOK + jc * 64) * 512 + 256 + t;
#pragma unroll 1
        for (int j0 = 0; j0 < 64; j0 += 8) {
            float va[8];
#pragma unroll
            for (int r = 0; r < 8; r++) va[r] = __bfloat162float(vbase[(size_t)(j0 + r) * 512]);
#pragma unroll
            for (int r = 0; r < 8; r++) {
                float4 aa = *(const float4*)&attn_s[j0 + r][0];
                float4 ab = *(const float4*)&attn_s[j0 + r][4];
                uacc[0] += aa.x * va[r]; uacc[1] += aa.y * va[r];
                uacc[2] += aa.z * va[r]; uacc[3] += aa.w * va[r];
                uacc[4] += ab.x * va[r]; uacc[5] += ab.y * va[r];
                uacc[6] += ab.z * va[r]; uacc[7] += ab.w * va[r];
            }
        }
#pragma unroll
        for (int i = 0; i < 8; i++)
            updp[((size_t)jc * SROWS + b * 8 + i) * 256 + t] = uacc[i];
        if (t < 8) {
            float r = 0.f;
#pragma unroll
            for (int ww = 0; ww < 8; ww++) r += rswarp[ww][t];
            rsp[jc * SROWS + b * 8 + t] = r;
        }
    }
}

// ---------------------------------------------------------------------------
// GRU, 16x32 units, updp reduction inline. grid (8, 16) = 128 blocks.
// ---------------------------------------------------------------------------
__global__ __launch_bounds__(256) void gru16_kernel(
    const float* __restrict__ updp, const float* __restrict__ rsp,
    const float* __restrict__ slots,
    const float* __restrict__ wih, const float* __restrict__ whh,
    const float* __restrict__ bih, const float* __restrict__ bhh,
    float* __restrict__ out) {
    __shared__ float Au[16][34], Ah[16][34];
    __shared__ float Bg[6][32][34];
    __shared__ float invrs[16];
    int t = threadIdx.x;
    int bm = blockIdx.y * 16, bn = blockIdx.x * 32;
    if (t < 16) {
        float rs = 0.f;
#pragma unroll
        for (int p = 0; p < NCHUNK; p++) rs += rsp[p * 256 + bm + t];
        invrs[t] = 1.0f / rs;
    }
    int ar = t >> 4, ak = (t & 15) * 2;
    int brr = t >> 3, bk = (t & 7) * 4;
    int tr = t >> 5, tc = t & 31;
    float acc[6][2];
#pragma unroll
    for (int g = 0; g < 6; g++) { acc[g][0] = 0.f; acc[g][1] = 0.f; }

    for (int kt = 0; kt < 8; kt++) {
        int k0 = kt * 32;
        __syncthreads();
        {
            size_t base = (size_t)(bm + ar) * 256 + k0 + ak;
            float sx = 0.f, sy = 0.f;
#pragma unroll
            for (int p = 0; p < NCHUNK; p++) {
                float2 v = *(const float2*)(updp + (size_t)p * 65536 + base);
                sx += v.x; sy += v.y;
            }
            float iv = invrs[ar];
            Au[ar][ak] = sx * iv; Au[ar][ak + 1] = sy * iv;
            float2 h2 = *(const float2*)(slots + base);
            Ah[ar][ak] = h2.x; Ah[ar][ak + 1] = h2.y;
#pragma unroll
            for (int g = 0; g < 6; g++) {
                const float* W = (g < 3) ? wih : whh;
                float4 w4 = *(const float4*)(W + (size_t)((g % 3) * 256 + bn + brr) * 256 + k0 + bk);
                Bg[g][brr][bk + 0] = w4.x; Bg[g][brr][bk + 1] = w4.y;
                Bg[g][brr][bk + 2] = w4.z; Bg[g][brr][bk + 3] = w4.w;
            }
        }
        __syncthreads();
#pragma unroll
        for (int kk = 0; kk < 32; kk += 2) {
            float2 u0 = *(const float2*)&Au[tr][kk];
            float2 u1 = *(const float2*)&Au[tr + 8][kk];
            float2 h0 = *(const float2*)&Ah[tr][kk];
            float2 h1v = *(const float2*)&Ah[tr + 8][kk];
#pragma unroll
            for (int g = 0; g < 6; g++) {
                float2 b2 = *(const float2*)&Bg[g][tc][kk];
                if (g < 3) {
                    acc[g][0] += u0.x * b2.x + u0.y * b2.y;
                    acc[g][1] += u1.x * b2.x + u1.y * b2.y;
                } else {
                    acc[g][0] += h0.x * b2.x + h0.y * b2.y;
                    acc[g][1] += h1v.x * b2.x + h1v.y * b2.y;
                }
            }
        }
    }
    int col = bn + tc;
#pragma unroll
    for (int r = 0; r < 2; r++) {
        int row = bm + tr + r * 8;
        float ir = acc[0][r] + bih[col];
        float iz = acc[1][r] + bih[col + 256];
        float in_ = acc[2][r] + bih[col + 512];
        float hr = acc[3][r] + bhh[col];
        float hz = acc[4][r] + bhh[col + 256];
        float hn = acc[5][r] + bhh[col + 512];
        float rg = sigmoidf_(ir + hr);
        float z = sigmoidf_(iz + hz);
        float nn = tanhf(in_ + rg * hn);
        float h = slots[(size_t)row * 256 + col];
        out[(size_t)row * 256 + col] = (1.0f - z) * nn + z * h;
    }
}

extern "C" void kernel_launch(void* const* d_in, const int* in_sizes, int n_in,
                              void* d_out, int out_size) {
    const float* inputs    = (const float*)d_in[0];
    const float* noise     = (const float*)d_in[1];
    const float* slots_mu  = (const float*)d_in[2];
    const float* slots_ls  = (const float*)d_in[3];
    const float* Wq        = (const float*)d_in[4];
    const float* Wk        = (const float*)d_in[5];
    const float* Wv        = (const float*)d_in[6];
    const float* gru_wih   = (const float*)d_in[7];
    const float* gru_whh   = (const float*)d_in[8];
    const float* gru_bih   = (const float*)d_in[9];
    const float* gru_bhh   = (const float*)d_in[10];
    const float* mlp_w1    = (const float*)d_in[11];
    const float* mlp_b1    = (const float*)d_in[12];
    const float* mlp_w2    = (const float*)d_in[13];
    const float* mlp_b2    = (const float*)d_in[14];
    const float* ln_in_g   = (const float*)d_in[15];
    const float* ln_in_b   = (const float*)d_in[16];
    const float* ln_s_g    = (const float*)d_in[17];
    const float* ln_s_b    = (const float*)d_in[18];
    const float* ln_ff_g   = (const float*)d_in[19];
    const float* ln_ff_b   = (const float*)d_in[20];

    float* S = nullptr;
    cudaGetSymbolAddress((void**)&S, g_scratch);
    __nv_bfloat16* wb = nullptr;
    cudaGetSymbolAddress((void**)&wb, g_wb);
    __nv_bfloat16* kv = (__nv_bfloat16*)(S + OFF_KV);
    float* slots = S + OFF_SLOTS;
    float* gbuf  = S + OFF_GBUF;
    float* qbuf  = S + OFF_Q;
    float* h1    = S + OFF_H1;
    float* updp  = S + OFF_UPDP;
    float* rsp   = S + OFF_RSP;
    float* S1kv  = S + OFF_S1KV;
    float* S2kv  = S + OFF_S2KV;
    float* Wqp   = S + OFF_WQP;
    float* S1q   = S + OFF_S1Q;
    float* S2q   = S + OFF_S2Q;
    float* W1p   = S + OFF_W1P;
    float* S1m   = S + OFF_S1M;
    float* S2m   = S + OFF_S2M;

    // 0: all preps + slot init
    setup_kernel<<<480, 256>>>(Wk, Wv, ln_in_g, ln_in_b, wb, S1kv, S2kv,
                               Wq, ln_s_g, ln_s_b, Wqp, S1q, S2q,
                               mlp_w1, ln_ff_g, ln_ff_b, W1p, S1m, S2m,
                               slots_mu, slots_ls, noise, slots);
    // 1: KV projection (bf16 out, 2 CTAs/SM)
    kv_mma_kernel<<<dim3(8, 256), 256>>>(inputs, wb, S1kv, S2kv, kv);

    for (int it = 0; it < ITERS; it++) {
        // q = LN(slots)@W'q * SCALE   (launch 2 on it0)
        gemm16_kernel<32, true, false, false, true><<<dim3(8, 16), 256>>>(
            slots, Wqp, S1q, S2q, nullptr, nullptr, qbuf, 256, 256);
        // attn partials                (launch 3 on it0 -> profiled)
        attn2_kernel<<<dim3(32, NCHUNK), 256>>>(qbuf, kv, updp, rsp);
        // GRU (updp reduce inline)
        gru16_kernel<<<dim3(8, 16), 256>>>(updp, rsp, slots,
            gru_wih, gru_whh, gru_bih, gru_bhh, gbuf);
        // mlp1 = relu(LN(gbuf)@W'1 + b1)
        gemm16_kernel<64, true, true, false, false><<<dim3(16, 16), 256>>>(
            gbuf, W1p, S1m, S2m, mlp_b1, nullptr, h1, 1024, 256);
        // mlp2 = h1@W2 + b2 + gbuf
        float* outp = (it == ITERS - 1) ? (float*)d_out : slots;
        gemm16_kernel<32, false, false, true, false><<<dim3(8, 16), 256>>>(
            h1, mlp_w2, nullptr, nullptr, mlp_b2, gbuf, outp, 256, 1024);
    }
}

// round 15
// speedup vs baseline: 2.2266x; 1.0175x over previous
#include <cuda_runtime.h>
#include <cuda_fp16.h>
#include <math.h>
#include <cstdint>

// ---------------------------------------------------------------------------
// SlotAttention: b=32, n=1024, c=256, d=256, S=8 slots, 3 iters.
// fp16 m16n8k16 mma.sync everywhere tensor-eligible; fp16 kv storage.
// attn: dots mma + softmax + updates mma (vT/attnT staged in smem).
// ---------------------------------------------------------------------------
#define NTOK 1024
#define ITERS 3
#define TOKROWS 32768
#define SROWS 256
#define SCALE_F 0.0625f
#define EPS_F 1e-8f
#define NCHUNK 16               // attn j-chunks of 64

// scratch arena (floats)
#define OFF_KV     0                                  // half[32768*512]
#define OFF_SLOTS  (OFF_KV + TOKROWS*256)
#define OFF_GBUF   (OFF_SLOTS + SROWS*256)
#define OFF_Q      (OFF_GBUF + SROWS*256)
#define OFF_H1     (OFF_Q + SROWS*256)                // 256*1024
#define OFF_UPDP   (OFF_H1 + SROWS*1024)              // 16*256*256
#define OFF_RSP    (OFF_UPDP + NCHUNK*SROWS*256)      // 16*256
#define OFF_S1KV   (OFF_RSP + NCHUNK*SROWS)           // 512
#define OFF_S2KV   (OFF_S1KV + 512)
#define OFF_WQP    (OFF_S2KV + 512)                   // 256*256 row-major
#define OFF_S1Q    (OFF_WQP + 256*256)
#define OFF_S2Q    (OFF_S1Q + 256)
#define OFF_W1P    (OFF_S2Q + 256)                    // 1024*256
#define OFF_S1M    (OFF_W1P + 1024*256)
#define OFF_S2M    (OFF_S1M + 1024)
#define SCRATCH_FLOATS (OFF_S2M + 1024)

__device__ __align__(16) float g_scratch[SCRATCH_FLOATS];
__device__ __align__(16) __half g_wb[512 * 256];

__device__ __forceinline__ float warp_sum(float v) {
#pragma unroll
    for (int o = 16; o > 0; o >>= 1) v += __shfl_xor_sync(0xffffffffu, v, o);
    return v;
}
__device__ __forceinline__ float grp8_sum(float v) {
    v += __shfl_xor_sync(0xffffffffu, v, 4);
    v += __shfl_xor_sync(0xffffffffu, v, 2);
    v += __shfl_xor_sync(0xffffffffu, v, 1);
    return v;
}
__device__ __forceinline__ float sigmoidf_(float x) { return 1.0f / (1.0f + __expf(-x)); }

__device__ __forceinline__ void mmaf16(float* d, const unsigned* a, const unsigned* b) {
    asm volatile("mma.sync.aligned.m16n8k16.row.col.f32.f16.f16.f32 "
        "{%0,%1,%2,%3}, {%4,%5,%6,%7}, {%8,%9}, {%0,%1,%2,%3};"
        : "+f"(d[0]), "+f"(d[1]), "+f"(d[2]), "+f"(d[3])
        : "r"(a[0]), "r"(a[1]), "r"(a[2]), "r"(a[3]), "r"(b[0]), "r"(b[1]));
}
__device__ __forceinline__ uint32_t packh2(float x, float y) {
    __half2 h = __floats2half2_rn(x, y);
    return *(uint32_t*)&h;
}

// ---------------------------------------------------------------------------
// setup: all weight preps + slot init in ONE kernel (grid 480).
// ---------------------------------------------------------------------------
__global__ void setup_kernel(
    const float* __restrict__ Wk, const float* __restrict__ Wv,
    const float* __restrict__ ln_in_g, const float* __restrict__ ln_in_b,
    __half* __restrict__ wb, float* __restrict__ S1kv, float* __restrict__ S2kv,
    const float* __restrict__ Wq, const float* __restrict__ ln_s_g, const float* __restrict__ ln_s_b,
    float* __restrict__ Wqp, float* __restrict__ S1q, float* __restrict__ S2q,
    const float* __restrict__ W1, const float* __restrict__ ln_ff_g, const float* __restrict__ ln_ff_b,
    float* __restrict__ W1p, float* __restrict__ S1m, float* __restrict__ S2m,
    const float* __restrict__ mu, const float* __restrict__ ls,
    const float* __restrict__ noise, float* __restrict__ slots) {
    int blk = blockIdx.x;
    int w = threadIdx.x >> 5, lane = threadIdx.x & 31;
    if (blk < 64) {
        int n = blk * 8 + w;
        const float* src = (n < 256) ? Wk + (size_t)n * 256 : Wv + (size_t)(n - 256) * 256;
        float s1 = 0.f, s2 = 0.f;
#pragma unroll
        for (int u = 0; u < 8; u++) {
            int c = u * 32 + lane;
            __half hf = __float2half(src[c] * ln_in_g[c]);
            wb[(size_t)n * 256 + c] = hf;
            s1 += __half2float(hf);
            s2 += src[c] * ln_in_b[c];
        }
        s1 = warp_sum(s1); s2 = warp_sum(s2);
        if (lane == 0) { S1kv[n] = s1; S2kv[n] = s2; }
    } else if (blk < 96) {
        int n = (blk - 64) * 8 + w;
        float s1 = 0.f, s2 = 0.f;
#pragma unroll
        for (int u = 0; u < 8; u++) {
            int c = u * 32 + lane;
            float wv = Wq[(size_t)n * 256 + c] * ln_s_g[c];
            Wqp[(size_t)n * 256 + c] = wv;
            s1 += wv;
            s2 += Wq[(size_t)n * 256 + c] * ln_s_b[c];
        }
        s1 = warp_sum(s1); s2 = warp_sum(s2);
        if (lane == 0) { S1q[n] = s1; S2q[n] = s2; }
    } else if (blk < 224) {
        int n = (blk - 96) * 8 + w;
        float s1 = 0.f, s2 = 0.f;
#pragma unroll
        for (int u = 0; u < 8; u++) {
            int c = u * 32 + lane;
            float wv = W1[(size_t)n * 256 + c] * ln_ff_g[c];
            W1p[(size_t)n * 256 + c] = wv;
            s1 += wv;
            s2 += W1[(size_t)n * 256 + c] * ln_ff_b[c];
        }
        s1 = warp_sum(s1); s2 = warp_sum(s2);
        if (lane == 0) { S1m[n] = s1; S2m[n] = s2; }
    } else {
        int idx = (blk - 224) * 256 + threadIdx.x;
        int d = idx & 255;
        slots[idx] = mu[d] + __expf(ls[d]) * noise[idx];
    }
}

// ---------------------------------------------------------------------------
// KV GEMM: C_fp16[32768, 512] = LN(x) @ [W'k;W'v]^T.
// BM=128 BN=64 BK=32, 2 CTAs/SM; fp16 m16n8k16; LN-fold epilogue, fp16 out.
// ---------------------------------------------------------------------------
__global__ __launch_bounds__(256, 2) void kv_mma_kernel(
    const float* __restrict__ x, const __half* __restrict__ wb,
    const float* __restrict__ S1, const float* __restrict__ S2,
    __half* __restrict__ C) {
    __shared__ uint32_t As[128][20];
    __shared__ uint32_t Bs[64][20];
    __shared__ float rowm[128], rowr[128];
    int t = threadIdx.x;
    int bm = blockIdx.y * 128, bn = blockIdx.x * 64;
    int w = t >> 5, lane = t & 31;
    int m0 = (w >> 2) * 64, n0 = (w & 3) * 16;
    int g = lane >> 2, tig = lane & 3;
    float acc[4][2][4];
#pragma unroll
    for (int a = 0; a < 4; a++)
#pragma unroll
        for (int bq = 0; bq < 2; bq++)
#pragma unroll
            for (int c = 0; c < 4; c++) acc[a][bq][c] = 0.f;

    int lm = t >> 3;
    int lkf = (t & 7) * 4;
    int lku = (t & 7) * 2;

    float4 ar[4]; uint2 br[2];
    float sA[4] = {0.f, 0.f, 0.f, 0.f}, s2A[4] = {0.f, 0.f, 0.f, 0.f};
#pragma unroll
    for (int r = 0; r < 4; r++)
        ar[r] = *(const float4*)(x + (size_t)(bm + r * 32 + lm) * 256 + lkf);
#pragma unroll
    for (int r = 0; r < 2; r++)
        br[r] = *(const uint2*)(wb + (size_t)(bn + r * 32 + lm) * 256 + lkf);

    for (int it = 0; it < 8; it++) {
#pragma unroll
        for (int r = 0; r < 4; r++) {
            sA[r] += ar[r].x + ar[r].y + ar[r].z + ar[r].w;
            s2A[r] += ar[r].x * ar[r].x + ar[r].y * ar[r].y + ar[r].z * ar[r].z + ar[r].w * ar[r].w;
        }
        __syncthreads();
#pragma unroll
        for (int r = 0; r < 4; r++) {
            int m = r * 32 + lm;
            As[m][lku + 0] = packh2(ar[r].x, ar[r].y);
            As[m][lku + 1] = packh2(ar[r].z, ar[r].w);
        }
#pragma unroll
        for (int r = 0; r < 2; r++) {
            int m = r * 32 + lm;
            Bs[m][lku + 0] = br[r].x;
            Bs[m][lku + 1] = br[r].y;
        }
        __syncthreads();
        if (it < 7) {
            int c = (it + 1) * 32 + lkf;
#pragma unroll
            for (int r = 0; r < 4; r++)
                ar[r] = *(const float4*)(x + (size_t)(bm + r * 32 + lm) * 256 + c);
#pragma unroll
            for (int r = 0; r < 2; r++)
                br[r] = *(const uint2*)(wb + (size_t)(bn + r * 32 + lm) * 256 + c);
        }
#pragma unroll
        for (int ks = 0; ks < 2; ks++) {
            unsigned a[4][4], b[2][2];
#pragma unroll
            for (int mt = 0; mt < 4; mt++) {
                int mr = m0 + mt * 16 + g;
                a[mt][0] = As[mr][ks * 8 + tig];
                a[mt][1] = As[mr + 8][ks * 8 + tig];
                a[mt][2] = As[mr][ks * 8 + tig + 4];
                a[mt][3] = As[mr + 8][ks * 8 + tig + 4];
            }
#pragma unroll
            for (int nt = 0; nt < 2; nt++) {
                int nr = n0 + nt * 8 + g;
                b[nt][0] = Bs[nr][ks * 8 + tig];
                b[nt][1] = Bs[nr][ks * 8 + tig + 4];
            }
#pragma unroll
            for (int mt = 0; mt < 4; mt++)
#pragma unroll
                for (int nt = 0; nt < 2; nt++)
                    mmaf16(acc[mt][nt], a[mt], b[nt]);
        }
    }
#pragma unroll
    for (int r = 0; r < 4; r++) {
        float s = grp8_sum(sA[r]);
        float s2 = grp8_sum(s2A[r]);
        if ((t & 7) == 0) {
            float m = s * (1.0f / 256.0f);
            float var = s2 * (1.0f / 256.0f) - m * m;
            rowm[r * 32 + lm] = m;
            rowr[r * 32 + lm] = rsqrtf(var + 1e-5f);
        }
    }
    __syncthreads();
#pragma unroll
    for (int mt = 0; mt < 4; mt++)
#pragma unroll
        for (int nt = 0; nt < 2; nt++) {
            int lr = m0 + mt * 16 + g;
            int col = bn + n0 + nt * 8 + tig * 2;
            float s1a = S1[col], s1b = S1[col + 1], s2a = S2[col], s2b = S2[col + 1];
            float m0v = rowm[lr], r0v = rowr[lr];
            float m1v = rowm[lr + 8], r1v = rowr[lr + 8];
            uint32_t o0 = packh2(r0v * acc[mt][nt][0] - r0v * m0v * s1a + s2a,
                                 r0v * acc[mt][nt][1] - r0v * m0v * s1b + s2b);
            uint32_t o1 = packh2(r1v * acc[mt][nt][2] - r1v * m1v * s1a + s2a,
                                 r1v * acc[mt][nt][3] - r1v * m1v * s1b + s2b);
            *(uint32_t*)(C + (size_t)(bm + lr) * 512 + col) = o0;
            *(uint32_t*)(C + (size_t)(bm + lr + 8) * 512 + col) = o1;
        }
}

// ---------------------------------------------------------------------------
// gemm16: 16-row x NC-col tiles, 256 threads, register-prefetched BK=32.
// ---------------------------------------------------------------------------
template<int NC, bool LNF, bool RELU, bool ADDOUT, bool QSC>
__global__ __launch_bounds__(256) void gemm16_kernel(
    const float* __restrict__ A, const float* __restrict__ B,
    const float* __restrict__ S1, const float* __restrict__ S2,
    const float* __restrict__ bias, const float* __restrict__ addsrc,
    float* __restrict__ C, int N, int K) {
    constexpr int CPT = NC / 32;
    __shared__ float As[16][34];
    __shared__ float Bs[NC][34];
    __shared__ float rowm[16], rowr[16];
    int t = threadIdx.x;
    int bm = blockIdx.y * 16, bn = blockIdx.x * NC;
    if (LNF) {
        int w = t >> 5, lane = t & 31;
#pragma unroll
        for (int rr = 0; rr < 2; rr++) {
            int row = w * 2 + rr;
            const float* p = A + (size_t)(bm + row) * 256;
            float s = 0.f, s2 = 0.f;
#pragma unroll
            for (int u = 0; u < 8; u++) { float v = p[lane + u * 32]; s += v; s2 += v * v; }
            s = warp_sum(s); s2 = warp_sum(s2);
            if (lane == 0) {
                float m = s * (1.0f / 256.0f);
                float var = s2 * (1.0f / 256.0f) - m * m;
                rowm[row] = m; rowr[row] = rsqrtf(var + 1e-5f);
            }
        }
    }
    int ar = t >> 4, ak = (t & 15) * 2;
    int brr = t >> 3, bk = (t & 7) * 4;
    int tr = t >> 5, tc = t & 31;
    float acc[2][CPT];
#pragma unroll
    for (int r = 0; r < 2; r++)
#pragma unroll
        for (int c = 0; c < CPT; c++) acc[r][c] = 0.f;

    float2 pa = *(const float2*)(A + (size_t)(bm + ar) * K + ak);
    float4 pb[CPT];
#pragma unroll
    for (int c = 0; c < CPT; c++)
        pb[c] = *(const float4*)(B + (size_t)(bn + c * 32 + brr) * K + bk);

    int KT = K >> 5;
    for (int kt = 0; kt < KT; kt++) {
        __syncthreads();
        As[ar][ak] = pa.x; As[ar][ak + 1] = pa.y;
#pragma unroll
        for (int c = 0; c < CPT; c++) {
            Bs[c * 32 + brr][bk + 0] = pb[c].x; Bs[c * 32 + brr][bk + 1] = pb[c].y;
            Bs[c * 32 + brr][bk + 2] = pb[c].z; Bs[c * 32 + brr][bk + 3] = pb[c].w;
        }
        __syncthreads();
        if (kt + 1 < KT) {
            int k0 = (kt + 1) * 32;
            pa = *(const float2*)(A + (size_t)(bm + ar) * K + k0 + ak);
#pragma unroll
            for (int c = 0; c < CPT; c++)
                pb[c] = *(const float4*)(B + (size_t)(bn + c * 32 + brr) * K + k0 + bk);
        }
#pragma unroll
        for (int kk = 0; kk < 32; kk += 2) {
            float2 a0 = *(const float2*)&As[tr][kk];
            float2 a1 = *(const float2*)&As[tr + 8][kk];
#pragma unroll
            for (int c = 0; c < CPT; c++) {
                float2 b2 = *(const float2*)&Bs[tc + c * 32][kk];
                acc[0][c] += a0.x * b2.x + a0.y * b2.y;
                acc[1][c] += a1.x * b2.x + a1.y * b2.y;
            }
        }
    }
#pragma unroll
    for (int r = 0; r < 2; r++) {
        int lr = tr + r * 8;
        int row = bm + lr;
#pragma unroll
        for (int c = 0; c < CPT; c++) {
            int col = bn + c * 32 + tc;
            float v = acc[r][c];
            if (LNF) { float m = rowm[lr], rs = rowr[lr]; v = rs * v - rs * m * S1[col] + S2[col]; }
            if (bias) v += bias[col];
            if (RELU) v = fmaxf(v, 0.f);
            if (QSC) v *= SCALE_F;
            if (ADDOUT) v += addsrc[(size_t)row * N + col];
            C[(size_t)row * N + col] = v;
        }
    }
}

// ---------------------------------------------------------------------------
// attention: dots mma + lane-parallel softmax + updates mma. fp16 kv.
// grid (32 batches, 16 j-chunks of 64).
// ---------------------------------------------------------------------------
__global__ __launch_bounds__(256) void attn2_kernel(
    const float* __restrict__ qbuf, const __half* __restrict__ kv,
    float* __restrict__ updp, float* __restrict__ rsp) {
    __shared__ uint32_t qs[8][132];          // fp16x2 pairs, row = slot
    __shared__ uint32_t attnT[8][34];        // fp16x2 j-pairs, row = slot
    __shared__ uint32_t vT[256][34];         // fp16x2 j-pairs, row = col (32 used)
    __shared__ float rswarp[8][8];
    int b = blockIdx.x, jc = blockIdx.y;
    int t = threadIdx.x, w = t >> 5, lane = t & 31;
    int g = lane >> 2, tig = lane & 3;

    // stage q as fp16 pairs: thread t -> slot row t>>5, 8 floats at (t&31)*8
    {
        int row = t >> 5, c8 = (t & 31) * 8;
        const float* qrow = qbuf + (size_t)(b * 8 + row) * 256 + c8;
        float4 f0 = *(const float4*)(qrow);
        float4 f1 = *(const float4*)(qrow + 4);
        int c4 = c8 >> 1;
        qs[row][c4 + 0] = packh2(f0.x, f0.y);
        qs[row][c4 + 1] = packh2(f0.z, f0.w);
        qs[row][c4 + 2] = packh2(f1.x, f1.y);
        qs[row][c4 + 3] = packh2(f1.z, f1.w);
    }
    // stage vT: thread t = col; pack j-pairs
    {
        const __half* vb = kv + ((size_t)b * NTOK + jc * 64) * 512 + 256 + t;
#pragma unroll 4
        for (int j2 = 0; j2 < 32; j2++) {
            __half lo = vb[(size_t)(2 * j2) * 512];
            __half hi = vb[(size_t)(2 * j2 + 1) * 512];
            __half2 p = __halves2half2(lo, hi);
            vT[t][j2] = *(uint32_t*)&p;
        }
    }
    __syncthreads();

    // dots mma: warp w -> j-tile [w*8, w*8+8); lane (g,tig):
    // c[0] = (slot g, j = w*8 + tig*2), c[1] = (slot g, j+1)
    {
        const uint32_t* kbase = (const uint32_t*)(kv + ((size_t)b * NTOK + jc * 64 + w * 8) * 512);
        float c[4] = {0.f, 0.f, 0.f, 0.f};
        uint32_t b0 = kbase[(size_t)g * 256 + tig];
        uint32_t b1 = kbase[(size_t)g * 256 + tig + 4];
#pragma unroll
        for (int ks = 0; ks < 16; ks++) {
            unsigned a[4], bfr[2];
            a[0] = qs[g][ks * 8 + tig];
            a[1] = 0u;
            a[2] = qs[g][ks * 8 + tig + 4];
            a[3] = 0u;
            bfr[0] = b0; bfr[1] = b1;
            if (ks < 15) {
                b0 = kbase[(size_t)g * 256 + (ks + 1) * 8 + tig];
                b1 = kbase[(size_t)g * 256 + (ks + 1) * 8 + tig + 4];
            }
            mmaf16(c, a, bfr);
        }
        // softmax over slots: reduce across lanes varying g (xor 4,8,16)
        float m0 = c[0], m1 = c[1];
#pragma unroll
        for (int o = 4; o <= 16; o <<= 1) {
            m0 = fmaxf(m0, __shfl_xor_sync(0xffffffffu, m0, o));
            m1 = fmaxf(m1, __shfl_xor_sync(0xffffffffu, m1, o));
        }
        float e0 = __expf(c[0] - m0), e1 = __expf(c[1] - m1);
        float s0 = e0, s1 = e1;
#pragma unroll
        for (int o = 4; o <= 16; o <<= 1) {
            s0 += __shfl_xor_sync(0xffffffffu, s0, o);
            s1 += __shfl_xor_sync(0xffffffffu, s1, o);
        }
        float a0 = e0 / s0 + EPS_F;
        float a1 = e1 / s1 + EPS_F;
        __half2 ah = __floats2half2_rn(a0, a1);
        attnT[g][w * 4 + tig] = *(uint32_t*)&ah;
        // row sums from the ROUNDED values (cancels fp16 quantization in u)
        float2 arf = __half22float2(ah);
        float rsa = arf.x + arf.y;
        rsa += __shfl_xor_sync(0xffffffffu, rsa, 1);
        rsa += __shfl_xor_sync(0xffffffffu, rsa, 2);
        if (tig == 0) rswarp[w][g] = rsa;
    }
    __syncthreads();

    // updates mma: out[col][slot], warp w -> m-tiles at w*32, w*32+16; K=64.
    {
        size_t outbase = (size_t)jc * SROWS + b * 8;
#pragma unroll
        for (int tt = 0; tt < 2; tt++) {
            int m0r = w * 32 + tt * 16;
            float c[4] = {0.f, 0.f, 0.f, 0.f};
#pragma unroll
            for (int ks = 0; ks < 4; ks++) {
                unsigned a[4], bfr[2];
                a[0] = vT[m0r + g][ks * 8 + tig];
                a[1] = vT[m0r + g + 8][ks * 8 + tig];
                a[2] = vT[m0r + g][ks * 8 + tig + 4];
                a[3] = vT[m0r + g + 8][ks * 8 + tig + 4];
                bfr[0] = attnT[g][ks * 8 + tig];
                bfr[1] = attnT[g][ks * 8 + tig + 4];
                mmaf16(c, a, bfr);
            }
            // lane (g,tig): cols m0r+g, m0r+g+8; slots 2tig, 2tig+1
            updp[(outbase + 2 * tig) * 256 + m0r + g] = c[0];
            updp[(outbase + 2 * tig + 1) * 256 + m0r + g] = c[1];
            updp[(outbase + 2 * tig) * 256 + m0r + g + 8] = c[2];
            updp[(outbase + 2 * tig + 1) * 256 + m0r + g + 8] = c[3];
        }
        if (t < 8) {
            float r = 0.f;
#pragma unroll
            for (int ww = 0; ww < 8; ww++) r += rswarp[ww][t];
            rsp[jc * SROWS + b * 8 + t] = r;
        }
    }
}

// ---------------------------------------------------------------------------
// GRU, 16x32 units, updp reduction inline. grid (8, 16) = 128 blocks.
// ---------------------------------------------------------------------------
__global__ __launch_bounds__(256) void gru16_kernel(
    const float* __restrict__ updp, const float* __restrict__ rsp,
    const float* __restrict__ slots,
    const float* __restrict__ wih, const float* __restrict__ whh,
    const float* __restrict__ bih, const float* __restrict__ bhh,
    float* __restrict__ out) {
    __shared__ float Au[16][34], Ah[16][34];
    __shared__ float Bg[6][32][34];
    __shared__ float invrs[16];
    int t = threadIdx.x;
    int bm = blockIdx.y * 16, bn = blockIdx.x * 32;
    if (t < 16) {
        float rs = 0.f;
#pragma unroll
        for (int p = 0; p < NCHUNK; p++) rs += rsp[p * 256 + bm + t];
        invrs[t] = 1.0f / rs;
    }
    int ar = t >> 4, ak = (t & 15) * 2;
    int brr = t >> 3, bk = (t & 7) * 4;
    int tr = t >> 5, tc = t & 31;
    float acc[6][2];
#pragma unroll
    for (int g = 0; g < 6; g++) { acc[g][0] = 0.f; acc[g][1] = 0.f; }

    for (int kt = 0; kt < 8; kt++) {
        int k0 = kt * 32;
        __syncthreads();
        {
            size_t base = (size_t)(bm + ar) * 256 + k0 + ak;
            float sx = 0.f, sy = 0.f;
#pragma unroll
            for (int p = 0; p < NCHUNK; p++) {
                float2 v = *(const float2*)(updp + (size_t)p * 65536 + base);
                sx += v.x; sy += v.y;
            }
            float iv = invrs[ar];
            Au[ar][ak] = sx * iv; Au[ar][ak + 1] = sy * iv;
            float2 h2 = *(const float2*)(slots + base);
            Ah[ar][ak] = h2.x; Ah[ar][ak + 1] = h2.y;
#pragma unroll
            for (int g = 0; g < 6; g++) {
                const float* W = (g < 3) ? wih : whh;
                float4 w4 = *(const float4*)(W + (size_t)((g % 3) * 256 + bn + brr) * 256 + k0 + bk);
                Bg[g][brr][bk + 0] = w4.x; Bg[g][brr][bk + 1] = w4.y;
                Bg[g][brr][bk + 2] = w4.z; Bg[g][brr][bk + 3] = w4.w;
            }
        }
        __syncthreads();
#pragma unroll
        for (int kk = 0; kk < 32; kk += 2) {
            float2 u0 = *(const float2*)&Au[tr][kk];
            float2 u1 = *(const float2*)&Au[tr + 8][kk];
            float2 h0 = *(const float2*)&Ah[tr][kk];
            float2 h1v = *(const float2*)&Ah[tr + 8][kk];
#pragma unroll
            for (int g = 0; g < 6; g++) {
                float2 b2 = *(const float2*)&Bg[g][tc][kk];
                if (g < 3) {
                    acc[g][0] += u0.x * b2.x + u0.y * b2.y;
                    acc[g][1] += u1.x * b2.x + u1.y * b2.y;
                } else {
                    acc[g][0] += h0.x * b2.x + h0.y * b2.y;
                    acc[g][1] += h1v.x * b2.x + h1v.y * b2.y;
                }
            }
        }
    }
    int col = bn + tc;
#pragma unroll
    for (int r = 0; r < 2; r++) {
        int row = bm + tr + r * 8;
        float ir = acc[0][r] + bih[col];
        float iz = acc[1][r] + bih[col + 256];
        float in_ = acc[2][r] + bih[col + 512];
        float hr = acc[3][r] + bhh[col];
        float hz = acc[4][r] + bhh[col + 256];
        float hn = acc[5][r] + bhh[col + 512];
        float rg = sigmoidf_(ir + hr);
        float z = sigmoidf_(iz + hz);
        float nn = tanhf(in_ + rg * hn);
        float h = slots[(size_t)row * 256 + col];
        out[(size_t)row * 256 + col] = (1.0f - z) * nn + z * h;
    }
}

extern "C" void kernel_launch(void* const* d_in, const int* in_sizes, int n_in,
                              void* d_out, int out_size) {
    const float* inputs    = (const float*)d_in[0];
    const float* noise     = (const float*)d_in[1];
    const float* slots_mu  = (const float*)d_in[2];
    const float* slots_ls  = (const float*)d_in[3];
    const float* Wq        = (const float*)d_in[4];
    const float* Wk        = (const float*)d_in[5];
    const float* Wv        = (const float*)d_in[6];
    const float* gru_wih   = (const float*)d_in[7];
    const float* gru_whh   = (const float*)d_in[8];
    const float* gru_bih   = (const float*)d_in[9];
    const float* gru_bhh   = (const float*)d_in[10];
    const float* mlp_w1    = (const float*)d_in[11];
    const float* mlp_b1    = (const float*)d_in[12];
    const float* mlp_w2    = (const float*)d_in[13];
    const float* mlp_b2    = (const float*)d_in[14];
    const float* ln_in_g   = (const float*)d_in[15];
    const float* ln_in_b   = (const float*)d_in[16];
    const float* ln_s_g    = (const float*)d_in[17];
    const float* ln_s_b    = (const float*)d_in[18];
    const float* ln_ff_g   = (const float*)d_in[19];
    const float* ln_ff_b   = (const float*)d_in[20];

    float* S = nullptr;
    cudaGetSymbolAddress((void**)&S, g_scratch);
    __half* wb = nullptr;
    cudaGetSymbolAddress((void**)&wb, g_wb);
    __half* kv   = (__half*)(S + OFF_KV);
    float* slots = S + OFF_SLOTS;
    float* gbuf  = S + OFF_GBUF;
    float* qbuf  = S + OFF_Q;
    float* h1    = S + OFF_H1;
    float* updp  = S + OFF_UPDP;
    float* rsp   = S + OFF_RSP;
    float* S1kv  = S + OFF_S1KV;
    float* S2kv  = S + OFF_S2KV;
    float* Wqp   = S + OFF_WQP;
    float* S1q   = S + OFF_S1Q;
    float* S2q   = S + OFF_S2Q;
    float* W1p   = S + OFF_W1P;
    float* S1m   = S + OFF_S1M;
    float* S2m   = S + OFF_S2M;

    // 0: all preps + slot init
    setup_kernel<<<480, 256>>>(Wk, Wv, ln_in_g, ln_in_b, wb, S1kv, S2kv,
                               Wq, ln_s_g, ln_s_b, Wqp, S1q, S2q,
                               mlp_w1, ln_ff_g, ln_ff_b, W1p, S1m, S2m,
                               slots_mu, slots_ls, noise, slots);
    // 1: KV projection (fp16 out, 2 CTAs/SM)
    kv_mma_kernel<<<dim3(8, 256), 256>>>(inputs, wb, S1kv, S2kv, kv);

    for (int it = 0; it < ITERS; it++) {
        // q = LN(slots)@W'q * SCALE   (launch 2 on it0)
        gemm16_kernel<32, true, false, false, true><<<dim3(8, 16), 256>>>(
            slots, Wqp, S1q, S2q, nullptr, nullptr, qbuf, 256, 256);
        // attn partials                (launch 3 on it0 -> profiled)
        attn2_kernel<<<dim3(32, NCHUNK), 256>>>(qbuf, kv, updp, rsp);
        // GRU (updp reduce inline)
        gru16_kernel<<<dim3(8, 16), 256>>>(updp, rsp, slots,
            gru_wih, gru_whh, gru_bih, gru_bhh, gbuf);
        // mlp1 = relu(LN(gbuf)@W'1 + b1)
        gemm16_kernel<64, true, true, false, false><<<dim3(16, 16), 256>>>(
            gbuf, W1p, S1m, S2m, mlp_b1, nullptr, h1, 1024, 256);
        // mlp2 = h1@W2 + b2 + gbuf
        float* outp = (it == ITERS - 1) ? (float*)d_out : slots;
        gemm16_kernel<32, false, false, true, false><<<dim3(8, 16), 256>>>(
            h1, mlp_w2, nullptr, nullptr, mlp_b2, gbuf, outp, 256, 1024);
    }
}